// round 8
// baseline (speedup 1.0000x reference)
#include <cuda_runtime.h>
#include <math.h>
#include <stdint.h>

#define BATCH 8
#define SEQ 1024
#define DIM 512
#define HEADS 16
#define HD 32
#define MROWS (BATCH*SEQ)   /* 8192 */
#define MLPH 2048
#define TBLN 3969           /* (2*32-1)^2 */

// ---------------- scratch (device globals; no allocations allowed) ----------
__device__ float g_h[MROWS * DIM];           // LN out (tf32, k-permuted)
__device__ float g_qkv[MROWS * 3 * DIM];     // q,k permuted; v plain (all tf32)
__device__ float g_attnout[MROWS * DIM];     // attention out (tf32, k-permuted)
__device__ float g_xres[MROWS * DIM];        // x + proj(attn)  (fp32, plain)
__device__ float g_mlp1[MROWS * MLPH];       // gelu(fc1) (tf32, k-permuted)
__device__ float g_w[3145728];               // transposed+permuted+rounded weights

#define W_QKV  0
#define W_PROJ 786432
#define W_FC1  1048576
#define W_FC2  2097152

// ---------------- helpers ----------------------------------------------------
__device__ __forceinline__ float to_tf32(float x) {
    uint32_t u;
    asm("cvt.rna.tf32.f32 %0, %1;" : "=r"(u) : "f"(x));
    return __uint_as_float(u);
}

__device__ __forceinline__ void mma_tf32(float* c, uint32_t a0, uint32_t a1,
                                         uint32_t a2, uint32_t a3,
                                         uint32_t b0, uint32_t b1) {
    asm volatile(
        "mma.sync.aligned.m16n8k8.row.col.f32.tf32.tf32.f32 "
        "{%0,%1,%2,%3}, {%4,%5,%6,%7}, {%8,%9}, {%0,%1,%2,%3};"
        : "+f"(c[0]), "+f"(c[1]), "+f"(c[2]), "+f"(c[3])
        : "r"(a0), "r"(a1), "r"(a2), "r"(a3), "r"(b0), "r"(b1));
}
#define U(x) __float_as_uint(x)

__device__ __forceinline__ void cp16(uint32_t s, const void* g) {
    asm volatile("cp.async.cg.shared.global [%0], [%1], 16;\n" :: "r"(s), "l"(g));
}
__device__ __forceinline__ void cp_commit() {
    asm volatile("cp.async.commit_group;\n");
}
template <int N> __device__ __forceinline__ void cp_wait() {
    asm volatile("cp.async.wait_group %0;\n" :: "n"(N));
}

// ---------------- weight transpose + 32-block k-permute + tf32 round --------
// in: [K][N] row-major.  out: [N][K], with k' = (k&3)*8 + (k>>2) inside each
// 32-block.  out[n][bk + c] = tf32(in[bk + 4*(c&7) + (c>>3)][n]).
__global__ void __launch_bounds__(256) cvt_t_kernel(const float* __restrict__ in,
                                                    float* __restrict__ out,
                                                    int K, int N)
{
    __shared__ float tile[32][33];
    const int bk = blockIdx.y * 32, bn = blockIdx.x * 32;
    const int tx = threadIdx.x, ty = threadIdx.y;
    #pragma unroll
    for (int i = 0; i < 4; i++)
        tile[ty + 8 * i][tx] = in[(size_t)(bk + ty + 8 * i) * N + bn + tx];
    __syncthreads();
    #pragma unroll
    for (int i = 0; i < 4; i++) {
        const int n = ty + 8 * i;
        out[(size_t)(bn + n) * K + bk + tx] =
            to_tf32(tile[4 * (tx & 7) + (tx >> 3)][n]);
    }
}

// ---------------- LayerNorm (tf32-rounded, k-permuted output) ---------------
__global__ void __launch_bounds__(128) ln_kernel(const float* __restrict__ x,
                                                 const float* __restrict__ g,
                                                 const float* __restrict__ b,
                                                 float* __restrict__ out)
{
    const int row = blockIdx.x;
    const int t = threadIdx.x;
    const float4 v = ((const float4*)(x + (size_t)row * DIM))[t];
    float s  = v.x + v.y + v.z + v.w;
    float s2 = v.x*v.x + v.y*v.y + v.z*v.z + v.w*v.w;
    #pragma unroll
    for (int o = 16; o > 0; o >>= 1) {
        s  += __shfl_xor_sync(0xffffffffu, s,  o);
        s2 += __shfl_xor_sync(0xffffffffu, s2, o);
    }
    __shared__ float rs[4], rs2[4];
    if ((t & 31) == 0) { rs[t >> 5] = s; rs2[t >> 5] = s2; }
    __syncthreads();
    s  = rs[0] + rs[1] + rs[2] + rs[3];
    s2 = rs2[0] + rs2[1] + rs2[2] + rs2[3];
    const float mean = s * (1.0f / DIM);
    const float var  = s2 * (1.0f / DIM) - mean * mean;
    const float inv  = rsqrtf(var + 1e-5f);
    const float4 gg = ((const float4*)g)[t];
    const float4 bb = ((const float4*)b)[t];
    float o4[4];
    o4[0] = to_tf32((v.x - mean) * inv * gg.x + bb.x);
    o4[1] = to_tf32((v.y - mean) * inv * gg.y + bb.y);
    o4[2] = to_tf32((v.z - mean) * inv * gg.z + bb.z);
    o4[3] = to_tf32((v.w - mean) * inv * gg.w + bb.w);
    // col 4t+c -> permuted (t>>3)*32 + 8c + (t&7)
    float* op = out + (size_t)row * DIM + (t >> 3) * 32 + (t & 7);
    #pragma unroll
    for (int c = 0; c < 4; c++) op[8 * c] = o4[c];
}

// ---------------- tf32 GEMM: permuted layouts, LDS.128, 64x64 warp tiles ----
// C[M,N] = epilogue(A[M,K] @ Wt[N,K]^T + bias [, R])
// A gmem: [M][K] k-permuted per 32-block.  Wt: [N][K] k-permuted.
// 128x128 block tile, BK=32, 128 thr = 4 warps (2x2), warp tile 64x64.
enum { EPI_BIAS = 0, EPI_GELU = 1, EPI_RES = 2 };
// PERM: 0 = plain fp32 out; 1 = permuted out; 2 = permuted iff col<1024 (qkv)

template <int EPI, int CVT, int PERM>
__global__ void __launch_bounds__(128, 2) gemm_tc(const float* __restrict__ A,
                                                  const float* __restrict__ Wt,
                                                  const float* __restrict__ bias,
                                                  const float* __restrict__ R,
                                                  float* __restrict__ C,
                                                  int M, int N, int K)
{
    __shared__ __align__(16) float As[2][128][36];   // [m][k']
    __shared__ __align__(16) float Bs[2][128][36];   // [n][k']

    const int bm = blockIdx.y * 128, bn = blockIdx.x * 128;
    const int tid = threadIdx.x;
    const int warp = tid >> 5, lane = tid & 31;
    const int wm = (warp & 1) * 64, wn = (warp >> 1) * 64;
    const int g = lane >> 2, t4 = lane & 3;

    // staging: fid = tid + i*128, i<8 per operand; row = fid>>3, kc = (fid&7)*4
    const int srow = tid >> 3, skc = (tid & 7) * 4;

    float acc[4][8][4];
    #pragma unroll
    for (int mi = 0; mi < 4; mi++)
        #pragma unroll
        for (int ni = 0; ni < 8; ni++)
            #pragma unroll
            for (int c = 0; c < 4; c++) acc[mi][ni][c] = 0.0f;

    const int nk = K >> 5;

    // prologue: stage 0
    #pragma unroll
    for (int i = 0; i < 8; i++) {
        const int r = srow + i * 16;
        cp16((uint32_t)__cvta_generic_to_shared(&As[0][r][skc]),
             A + (size_t)(bm + r) * K + skc);
        cp16((uint32_t)__cvta_generic_to_shared(&Bs[0][r][skc]),
             Wt + (size_t)(bn + r) * K + skc);
    }
    cp_commit();

    for (int kt = 0; kt < nk; kt++) {
        const int s = kt & 1;
        if (kt + 1 < nk) {
            const int k0 = (kt + 1) * 32, sn = s ^ 1;
            #pragma unroll
            for (int i = 0; i < 8; i++) {
                const int r = srow + i * 16;
                cp16((uint32_t)__cvta_generic_to_shared(&As[sn][r][skc]),
                     A + (size_t)(bm + r) * K + k0 + skc);
                cp16((uint32_t)__cvta_generic_to_shared(&Bs[sn][r][skc]),
                     Wt + (size_t)(bn + r) * K + k0 + skc);
            }
            cp_commit();
            cp_wait<1>();
        } else {
            cp_wait<0>();
        }
        __syncthreads();

        #pragma unroll
        for (int h2 = 0; h2 < 2; h2++) {
            const int kc = 8 * t4 + 4 * h2;
            float4 a4[4][2];
            #pragma unroll
            for (int mi = 0; mi < 4; mi++) {
                a4[mi][0] = *(const float4*)&As[s][wm + 16 * mi + g][kc];
                a4[mi][1] = *(const float4*)&As[s][wm + 16 * mi + g + 8][kc];
            }
            #pragma unroll
            for (int ni = 0; ni < 8; ni++) {
                const float4 b4 = *(const float4*)&Bs[s][wn + 8 * ni + g][kc];
                #pragma unroll
                for (int mi = 0; mi < 4; mi++) {
                    mma_tf32(acc[mi][ni], U(a4[mi][0].x), U(a4[mi][1].x),
                             U(a4[mi][0].y), U(a4[mi][1].y), U(b4.x), U(b4.y));
                    mma_tf32(acc[mi][ni], U(a4[mi][0].z), U(a4[mi][1].z),
                             U(a4[mi][0].w), U(a4[mi][1].w), U(b4.z), U(b4.w));
                }
            }
        }
        __syncthreads();
    }

    // epilogue
    #pragma unroll
    for (int mi = 0; mi < 4; mi++) {
        const int r0 = bm + wm + mi * 16 + g;
        #pragma unroll
        for (int ni = 0; ni < 8; ni++) {
            const int col = bn + wn + ni * 8 + t4 * 2;
            const float b0 = bias[col], b1 = bias[col + 1];
            float v[4];
            v[0] = acc[mi][ni][0] + b0;
            v[1] = acc[mi][ni][1] + b1;
            v[2] = acc[mi][ni][2] + b0;
            v[3] = acc[mi][ni][3] + b1;
            if (EPI == EPI_GELU) {
                #pragma unroll
                for (int c = 0; c < 4; c++)
                    v[c] = 0.5f * v[c] * (1.0f + erff(v[c] * 0.70710678118654752f));
            }
            if (EPI == EPI_RES) {
                const float2 r4a = *(const float2*)(R + (size_t)r0 * N + col);
                const float2 r4b = *(const float2*)(R + (size_t)(r0 + 8) * N + col);
                v[0] += r4a.x; v[1] += r4a.y;
                v[2] += r4b.x; v[3] += r4b.y;
            }
            if (CVT) {
                #pragma unroll
                for (int c = 0; c < 4; c++) v[c] = to_tf32(v[c]);
            }
            const bool perm = (PERM == 1) || (PERM == 2 && col < 1024);
            if (perm) {
                const int p = (col & ~31) + 16 * (t4 & 1) + 2 * (ni & 3) + (t4 >> 1);
                C[(size_t)r0 * N + p]           = v[0];
                C[(size_t)r0 * N + p + 8]       = v[1];
                C[(size_t)(r0 + 8) * N + p]     = v[2];
                C[(size_t)(r0 + 8) * N + p + 8] = v[3];
            } else {
                *(float2*)(C + (size_t)r0 * N + col)       = make_float2(v[0], v[1]);
                *(float2*)(C + (size_t)(r0 + 8) * N + col) = make_float2(v[2], v[3]);
            }
        }
    }
}

// ---------------- Flash attention: LDS.128 K-frags, smem bias table ---------
// Block: 128 queries x one (b,h); 8 warps x 16 q-rows; 64-key tiles.
__global__ void __launch_bounds__(256, 2) attn_tc_kernel(const float* __restrict__ table,
                                                         float* __restrict__ out)
{
    __shared__ __align__(16) float Ks[2][64][36];
    __shared__ __align__(16) float Vs[2][64][36];
    __shared__ float Ps[8][16][68];
    __shared__ float tbl[TBLN];

    const int b = blockIdx.z, h = blockIdx.y, q0 = blockIdx.x * 128;
    const int tid = threadIdx.x;
    const int warp = tid >> 5, lane = tid & 31;
    const int g = lane >> 2, t4 = lane & 3;
    const int wq = warp * 16;

    const float scale = 0.17677669529663687f; // 1/sqrt(32)

    // K/V staging map
    const int key0 = tid >> 3, c40 = (tid & 7) * 4;

    // prologue: stage tile 0 (start it before table loads)
    #pragma unroll
    for (int i = 0; i < 2; i++) {
        const int key = key0 + i * 32;
        const float* kp = g_qkv + ((size_t)(b * SEQ + key)) * (3 * DIM)
                          + DIM + h * HD + c40;
        cp16((uint32_t)__cvta_generic_to_shared(&Ks[0][key][c40]), kp);
        cp16((uint32_t)__cvta_generic_to_shared(&Vs[0][key][c40]), kp + DIM);
    }
    cp_commit();

    // per-head bias table column -> smem
    for (int i = tid; i < TBLN; i += 256) tbl[i] = table[i * HEADS + h];

    // ---- Q fragments: permuted gmem -> 4 float4 loads ----
    uint32_t qf[4][4];
    {
        const float* q0p = g_qkv + ((size_t)(b * SEQ + q0 + wq + g)) * (3 * DIM) + h * HD;
        const float* q1p = q0p + 8 * (3 * DIM);
        const float4 A0 = *(const float4*)(q0p + 8 * t4);
        const float4 A1 = *(const float4*)(q0p + 8 * t4 + 4);
        const float4 C0 = *(const float4*)(q1p + 8 * t4);
        const float4 C1 = *(const float4*)(q1p + 8 * t4 + 4);
        qf[0][0] = U(to_tf32(A0.x * scale)); qf[0][1] = U(to_tf32(C0.x * scale));
        qf[0][2] = U(to_tf32(A0.y * scale)); qf[0][3] = U(to_tf32(C0.y * scale));
        qf[1][0] = U(to_tf32(A0.z * scale)); qf[1][1] = U(to_tf32(C0.z * scale));
        qf[1][2] = U(to_tf32(A0.w * scale)); qf[1][3] = U(to_tf32(C0.w * scale));
        qf[2][0] = U(to_tf32(A1.x * scale)); qf[2][1] = U(to_tf32(C1.x * scale));
        qf[2][2] = U(to_tf32(A1.y * scale)); qf[2][3] = U(to_tf32(C1.y * scale));
        qf[3][0] = U(to_tf32(A1.z * scale)); qf[3][1] = U(to_tf32(C1.z * scale));
        qf[3][2] = U(to_tf32(A1.w * scale)); qf[3][3] = U(to_tf32(C1.w * scale));
    }

    // rel-index bases: ri = (ly - my)*63 + (lx - mx) + 1984
    const int l0 = q0 + wq + g, l1 = l0 + 8;
    const int Cb0 = (l0 >> 5) * 63 + (l0 & 31) + 1984;
    const int Cb1 = (l1 >> 5) * 63 + (l1 & 31) + 1984;

    float m0 = -1e30f, m1 = -1e30f, li0 = 0.0f, li1 = 0.0f;
    float acc_o[4][4];
    #pragma unroll
    for (int ni = 0; ni < 4; ni++)
        #pragma unroll
        for (int c = 0; c < 4; c++) acc_o[ni][c] = 0.0f;

    for (int it = 0; it < SEQ / 64; it++) {
        const int s = it & 1;
        const int k0 = it * 64;
        if (it + 1 < SEQ / 64) {
            const int sn = s ^ 1;
            #pragma unroll
            for (int i = 0; i < 2; i++) {
                const int key = key0 + i * 32;
                const float* kp = g_qkv + ((size_t)(b * SEQ + k0 + 64 + key)) * (3 * DIM)
                                  + DIM + h * HD + c40;
                cp16((uint32_t)__cvta_generic_to_shared(&Ks[sn][key][c40]), kp);
                cp16((uint32_t)__cvta_generic_to_shared(&Vs[sn][key][c40]), kp + DIM);
            }
            cp_commit();
            cp_wait<1>();
        } else {
            cp_wait<0>();
        }
        __syncthreads();

        // ---- S = Q @ K^T ----
        float sacc[8][4];
        #pragma unroll
        for (int ni = 0; ni < 8; ni++)
            #pragma unroll
            for (int c = 0; c < 4; c++) sacc[ni][c] = 0.0f;
        #pragma unroll
        for (int h2 = 0; h2 < 2; h2++) {
            const int kc = 8 * t4 + 4 * h2;
            #pragma unroll
            for (int ni = 0; ni < 8; ni++) {
                const float4 kf = *(const float4*)&Ks[s][ni * 8 + g][kc];
                mma_tf32(sacc[ni], qf[2*h2][0], qf[2*h2][1], qf[2*h2][2], qf[2*h2][3],
                         U(kf.x), U(kf.y));
                mma_tf32(sacc[ni], qf[2*h2+1][0], qf[2*h2+1][1], qf[2*h2+1][2], qf[2*h2+1][3],
                         U(kf.z), U(kf.w));
            }
        }
        // ---- + rel-pos bias from smem table ----
        {
            const int base0 = Cb0 - (k0 >> 5) * 63;
            const int base1 = Cb1 - (k0 >> 5) * 63;
            #pragma unroll
            for (int ni = 0; ni < 8; ni++) {
                const int off = (ni >> 2) * 63 + 8 * (ni & 3) + 2 * t4;
                sacc[ni][0] += tbl[base0 - off];
                sacc[ni][1] += tbl[base0 - off - 1];
                sacc[ni][2] += tbl[base1 - off];
                sacc[ni][3] += tbl[base1 - off - 1];
            }
        }

        // ---- online softmax ----
        float vmax0 = -1e30f, vmax1 = -1e30f;
        #pragma unroll
        for (int ni = 0; ni < 8; ni++) {
            vmax0 = fmaxf(vmax0, fmaxf(sacc[ni][0], sacc[ni][1]));
            vmax1 = fmaxf(vmax1, fmaxf(sacc[ni][2], sacc[ni][3]));
        }
        #pragma unroll
        for (int o = 1; o <= 2; o <<= 1) {
            vmax0 = fmaxf(vmax0, __shfl_xor_sync(0xffffffffu, vmax0, o));
            vmax1 = fmaxf(vmax1, __shfl_xor_sync(0xffffffffu, vmax1, o));
        }
        const float nm0 = fmaxf(m0, vmax0);
        const float nm1 = fmaxf(m1, vmax1);
        const float corr0 = __expf(m0 - nm0);
        const float corr1 = __expf(m1 - nm1);
        m0 = nm0; m1 = nm1;
        float rs0 = 0.0f, rs1 = 0.0f;

        __syncwarp();
        #pragma unroll
        for (int ni = 0; ni < 8; ni++) {
            const float p0 = __expf(sacc[ni][0] - m0);
            const float p1 = __expf(sacc[ni][1] - m0);
            const float p2 = __expf(sacc[ni][2] - m1);
            const float p3 = __expf(sacc[ni][3] - m1);
            rs0 += p0 + p1; rs1 += p2 + p3;
            const int col = ni * 8 + t4 * 2;
            *(float2*)&Ps[warp][g][col]     = make_float2(to_tf32(p0), to_tf32(p1));
            *(float2*)&Ps[warp][g + 8][col] = make_float2(to_tf32(p2), to_tf32(p3));
        }
        li0 = li0 * corr0 + rs0;
        li1 = li1 * corr1 + rs1;
        #pragma unroll
        for (int ni = 0; ni < 4; ni++) {
            acc_o[ni][0] *= corr0; acc_o[ni][1] *= corr0;
            acc_o[ni][2] *= corr1; acc_o[ni][3] *= corr1;
        }
        __syncwarp();

        // ---- O += P @ V ----
        #pragma unroll
        for (int ks = 0; ks < 8; ks++) {
            const int kk = ks * 8;
            uint32_t a0 = U(Ps[warp][g][kk + t4]);
            uint32_t a1 = U(Ps[warp][g + 8][kk + t4]);
            uint32_t a2 = U(Ps[warp][g][kk + t4 + 4]);
            uint32_t a3 = U(Ps[warp][g + 8][kk + t4 + 4]);
            #pragma unroll
            for (int ni = 0; ni < 4; ni++) {
                const uint32_t b0 = U(Vs[s][kk + t4][ni * 8 + g]);
                const uint32_t b1 = U(Vs[s][kk + t4 + 4][ni * 8 + g]);
                mma_tf32(acc_o[ni], a0, a1, a2, a3, b0, b1);
            }
        }
        __syncthreads();
    }

    // ---- finalize: rounded + k-permuted output (feeds proj-A) ----
    #pragma unroll
    for (int o = 1; o <= 2; o <<= 1) {
        li0 += __shfl_xor_sync(0xffffffffu, li0, o);
        li1 += __shfl_xor_sync(0xffffffffu, li1, o);
    }
    const float inv0 = 1.0f / li0;
    const float inv1 = 1.0f / li1;
    float* o0p = out + ((size_t)(b * SEQ + q0 + wq + g)) * DIM + h * HD;
    float* o1p = o0p + 8 * DIM;
    #pragma unroll
    for (int ni = 0; ni < 4; ni++) {
        const int p = 16 * (t4 & 1) + 2 * ni + (t4 >> 1);
        o0p[p]     = to_tf32(acc_o[ni][0] * inv0);
        o0p[p + 8] = to_tf32(acc_o[ni][1] * inv0);
        o1p[p]     = to_tf32(acc_o[ni][2] * inv1);
        o1p[p + 8] = to_tf32(acc_o[ni][3] * inv1);
    }
}

// ---------------- launch -----------------------------------------------------
extern "C" void kernel_launch(void* const* d_in, const int* in_sizes, int n_in,
                              void* d_out, int out_size)
{
    const float* x      = (const float*)d_in[0];
    const float* table  = (const float*)d_in[2];
    const float* qkv_w  = (const float*)d_in[3];
    const float* qkv_b  = (const float*)d_in[4];
    const float* proj_w = (const float*)d_in[5];
    const float* proj_b = (const float*)d_in[6];
    const float* n1_g   = (const float*)d_in[7];
    const float* n1_b   = (const float*)d_in[8];
    const float* n2_g   = (const float*)d_in[9];
    const float* n2_b   = (const float*)d_in[10];
    const float* fc1_w  = (const float*)d_in[11];
    const float* fc1_b  = (const float*)d_in[12];
    const float* fc2_w  = (const float*)d_in[13];
    const float* fc2_b  = (const float*)d_in[14];
    float* out = (float*)d_out;

    float *h, *qkv, *attnout, *xres, *mlp1, *w;
    cudaGetSymbolAddress((void**)&h,       g_h);
    cudaGetSymbolAddress((void**)&qkv,     g_qkv);
    cudaGetSymbolAddress((void**)&attnout, g_attnout);
    cudaGetSymbolAddress((void**)&xres,    g_xres);
    cudaGetSymbolAddress((void**)&mlp1,    g_mlp1);
    cudaGetSymbolAddress((void**)&w,       g_w);

    dim3 tb(32, 8);
    // 0. transpose + permute + round weights
    cvt_t_kernel<<<dim3(48, 16), tb>>>(qkv_w,  w + W_QKV,  DIM,  3 * DIM);
    cvt_t_kernel<<<dim3(16, 16), tb>>>(proj_w, w + W_PROJ, DIM,  DIM);
    cvt_t_kernel<<<dim3(64, 16), tb>>>(fc1_w,  w + W_FC1,  DIM,  MLPH);
    cvt_t_kernel<<<dim3(16, 64), tb>>>(fc2_w,  w + W_FC2,  MLPH, DIM);
    // 1. h = LN1(x) (rounded, permuted)
    ln_kernel<<<MROWS, 128>>>(x, n1_g, n1_b, h);
    // 2. qkv = round(h @ qkv_w + qkv_b); q,k permuted, v plain
    gemm_tc<EPI_BIAS, 1, 2><<<dim3(12, 64), 128>>>(h, w + W_QKV, qkv_b, nullptr, qkv,
                                                   MROWS, 3 * DIM, DIM);
    // 3. flash attention -> rounded permuted [B, L, C]
    attn_tc_kernel<<<dim3(8, HEADS, BATCH), 256>>>(table, attnout);
    // 4. xres = x + attnout @ proj_w + proj_b  (fp32 plain)
    gemm_tc<EPI_RES, 0, 0><<<dim3(4, 64), 128>>>(attnout, w + W_PROJ, proj_b, x, xres,
                                                 MROWS, DIM, DIM);
    // 5. h = LN2(xres) (rounded, permuted)
    ln_kernel<<<MROWS, 128>>>(xres, n2_g, n2_b, h);
    // 6. mlp1 = round(gelu(h @ fc1_w + fc1_b)) permuted
    gemm_tc<EPI_GELU, 1, 1><<<dim3(16, 64), 128>>>(h, w + W_FC1, fc1_b, nullptr, mlp1,
                                                   MROWS, MLPH, DIM);
    // 7. out = xres + mlp1 @ fc2_w + fc2_b  (fp32 plain)
    gemm_tc<EPI_RES, 0, 0><<<dim3(4, 64), 128>>>(mlp1, w + W_FC2, fc2_b, xres, out,
                                                 MROWS, DIM, MLPH);
}

// round 10
// speedup vs baseline: 1.4784x; 1.4784x over previous
#include <cuda_runtime.h>
#include <cuda_fp16.h>
#include <math.h>
#include <stdint.h>

#define BATCH 8
#define SEQ 1024
#define DIM 512
#define HEADS 16
#define HD 32
#define MROWS (BATCH*SEQ)   /* 8192 */
#define MLPH 2048

// ---------------- scratch (device globals; no allocations allowed) ----------
__device__ __align__(256) __half g_h[MROWS * DIM];         // LN out (fp16)
__device__ __align__(256) __half g_qkv[MROWS * 3 * DIM];   // q|k|v (fp16)
__device__ __align__(256) __half g_vt[BATCH * HEADS * HD * SEQ]; // V^T per (b,h)
__device__ __align__(256) __half g_attnout[MROWS * DIM];   // attention out (fp16)
__device__ __align__(256) __half g_mlp1[MROWS * MLPH];     // gelu(fc1) (fp16)
__device__ __align__(256) __half g_w[3145728];             // [N][K] fp16 weights
__device__ float g_bias[HEADS * SEQ * SEQ];                // expanded rel-pos bias
__device__ float g_xres[MROWS * DIM];                      // x + proj(attn) fp32

#define W_QKV  0
#define W_PROJ 786432
#define W_FC1  1048576
#define W_FC2  2097152

// ---------------- helpers ----------------------------------------------------
#define U(x) __float_as_uint(x)

__device__ __forceinline__ void mma_f16(float* c, uint32_t a0, uint32_t a1,
                                        uint32_t a2, uint32_t a3,
                                        uint32_t b0, uint32_t b1) {
    asm volatile(
        "mma.sync.aligned.m16n8k16.row.col.f32.f16.f16.f32 "
        "{%0,%1,%2,%3}, {%4,%5,%6,%7}, {%8,%9}, {%0,%1,%2,%3};"
        : "+f"(c[0]), "+f"(c[1]), "+f"(c[2]), "+f"(c[3])
        : "r"(a0), "r"(a1), "r"(a2), "r"(a3), "r"(b0), "r"(b1));
}

__device__ __forceinline__ void cp16(uint32_t s, const void* g) {
    asm volatile("cp.async.cg.shared.global [%0], [%1], 16;\n" :: "r"(s), "l"(g));
}
__device__ __forceinline__ void cp_commit() {
    asm volatile("cp.async.commit_group;\n");
}
template <int N> __device__ __forceinline__ void cp_wait() {
    asm volatile("cp.async.wait_group %0;\n" :: "n"(N));
}
__device__ __forceinline__ uint32_t smem_u32(const void* p) {
    uint32_t a;
    asm("{ .reg .u64 t; cvta.to.shared.u64 t, %1; cvt.u32.u64 %0, t; }"
        : "=r"(a) : "l"(p));
    return a;
}
__device__ __forceinline__ uint32_t ld_h2(const __half* p) {
    return *(const uint32_t*)p;
}

// ---------------- weight transpose + fp16 convert ----------------------------
// in: [K][N] fp32 row-major.  out: [N][K] fp16
__global__ void __launch_bounds__(256) cvt_t_kernel(const float* __restrict__ in,
                                                    __half* __restrict__ out,
                                                    int K, int N)
{
    __shared__ float tile[32][33];
    const int bk = blockIdx.y * 32, bn = blockIdx.x * 32;
    const int tx = threadIdx.x, ty = threadIdx.y;
    #pragma unroll
    for (int i = 0; i < 4; i++)
        tile[ty + 8 * i][tx] = in[(size_t)(bk + ty + 8 * i) * N + bn + tx];
    __syncthreads();
    #pragma unroll
    for (int i = 0; i < 4; i++) {
        const int n = ty + 8 * i;
        out[(size_t)(bn + n) * K + bk + tx] = __float2half_rn(tile[tx][n]);
    }
}

// ---------------- V transpose: g_qkv v-section -> Vt[b][h][d][seq] -----------
__global__ void __launch_bounds__(256) vt_kernel()
{
    __shared__ __half tile[32][34];
    const int m0 = blockIdx.x * 32, h = blockIdx.y, b = blockIdx.z;
    const int tx = threadIdx.x, ty = threadIdx.y;
    const __half* in = g_qkv + (size_t)(b * SEQ) * (3 * DIM) + 2 * DIM + h * HD;
    #pragma unroll
    for (int i = 0; i < 4; i++)
        tile[ty + 8 * i][tx] = in[(size_t)(m0 + ty + 8 * i) * (3 * DIM) + tx];
    __syncthreads();
    __half* out = g_vt + ((size_t)(b * HEADS + h) * HD) * SEQ + m0;
    #pragma unroll
    for (int i = 0; i < 4; i++) {
        const int d = ty + 8 * i;
        out[(size_t)d * SEQ + tx] = tile[tx][d];
    }
}

// ---------------- LayerNorm (fp16 output) ------------------------------------
__global__ void __launch_bounds__(128) ln_kernel(const float* __restrict__ x,
                                                 const float* __restrict__ g,
                                                 const float* __restrict__ b,
                                                 __half* __restrict__ out)
{
    const int row = blockIdx.x;
    const int t = threadIdx.x;
    const float4 v = ((const float4*)(x + (size_t)row * DIM))[t];
    float s  = v.x + v.y + v.z + v.w;
    float s2 = v.x*v.x + v.y*v.y + v.z*v.z + v.w*v.w;
    #pragma unroll
    for (int o = 16; o > 0; o >>= 1) {
        s  += __shfl_xor_sync(0xffffffffu, s,  o);
        s2 += __shfl_xor_sync(0xffffffffu, s2, o);
    }
    __shared__ float rs[4], rs2[4];
    if ((t & 31) == 0) { rs[t >> 5] = s; rs2[t >> 5] = s2; }
    __syncthreads();
    s  = rs[0] + rs[1] + rs[2] + rs[3];
    s2 = rs2[0] + rs2[1] + rs2[2] + rs2[3];
    const float mean = s * (1.0f / DIM);
    const float var  = s2 * (1.0f / DIM) - mean * mean;
    const float inv  = rsqrtf(var + 1e-5f);
    const float4 gg = ((const float4*)g)[t];
    const float4 bb = ((const float4*)b)[t];
    __half2* op = (__half2*)(out + (size_t)row * DIM + 4 * t);
    op[0] = __floats2half2_rn((v.x - mean) * inv * gg.x + bb.x,
                              (v.y - mean) * inv * gg.y + bb.y);
    op[1] = __floats2half2_rn((v.z - mean) * inv * gg.z + bb.z,
                              (v.w - mean) * inv * gg.w + bb.w);
}

// ---------------- bias expand ------------------------------------------------
__global__ void __launch_bounds__(256) bias_expand_kernel(const int* __restrict__ rel,
                                                          const float* __restrict__ table)
{
    const unsigned idx = blockIdx.x * 256u + threadIdx.x;
    const int m = idx & 1023;
    const int l = (idx >> 10) & 1023;
    const int h = idx >> 20;
    const int ri = rel[l * SEQ + m];
    g_bias[idx] = table[ri * HEADS + h];
}

// ---------------- fp16 tensor-core GEMM --------------------------------------
// C[M,N] = epilogue(A[M,K] @ Wt[N,K]^T + bias [, R])
// 128x128 block, BK=32, 128 thr = 4 warps (2x2), warp tile 64x64, m16n8k16.
enum { EPI_BIAS = 0, EPI_GELU = 1, EPI_RES = 2 };

template <int EPI, int OUTH>
__global__ void __launch_bounds__(128, 2) gemm_h(const __half* __restrict__ A,
                                                 const __half* __restrict__ Wt,
                                                 const float* __restrict__ bias,
                                                 const float* __restrict__ R,
                                                 float* __restrict__ Cf,
                                                 __half* __restrict__ Ch,
                                                 int M, int N, int K)
{
    __shared__ __align__(16) __half As[2][128][40];   // [m][k]
    __shared__ __align__(16) __half Bs[2][128][40];   // [n][k]

    const int bm = blockIdx.y * 128, bn = blockIdx.x * 128;
    const int tid = threadIdx.x;
    const int warp = tid >> 5, lane = tid & 31;
    const int wm = (warp & 1) * 64, wn = (warp >> 1) * 64;
    const int g = lane >> 2, t4 = lane & 3;

    // staging: 128 rows x 64B (BK=32 halfs) = 512 chunks per operand, 4/thread
    const int srow = tid >> 2, sch = (tid & 3) * 8;

    float acc[4][8][4];
    #pragma unroll
    for (int mi = 0; mi < 4; mi++)
        #pragma unroll
        for (int ni = 0; ni < 8; ni++)
            #pragma unroll
            for (int c = 0; c < 4; c++) acc[mi][ni][c] = 0.0f;

    const int nk = K >> 5;

    #pragma unroll
    for (int i = 0; i < 4; i++) {
        const int r = srow + i * 32;
        cp16(smem_u32(&As[0][r][sch]), A + (size_t)(bm + r) * K + sch);
        cp16(smem_u32(&Bs[0][r][sch]), Wt + (size_t)(bn + r) * K + sch);
    }
    cp_commit();

    for (int kt = 0; kt < nk; kt++) {
        const int s = kt & 1;
        if (kt + 1 < nk) {
            const int k0 = (kt + 1) * 32, sn = s ^ 1;
            #pragma unroll
            for (int i = 0; i < 4; i++) {
                const int r = srow + i * 32;
                cp16(smem_u32(&As[sn][r][sch]), A + (size_t)(bm + r) * K + k0 + sch);
                cp16(smem_u32(&Bs[sn][r][sch]), Wt + (size_t)(bn + r) * K + k0 + sch);
            }
            cp_commit();
            cp_wait<1>();
        } else {
            cp_wait<0>();
        }
        __syncthreads();

        #pragma unroll
        for (int ks = 0; ks < 2; ks++) {
            const int kc = 16 * ks + 2 * t4;
            uint32_t a[4][4];
            #pragma unroll
            for (int mi = 0; mi < 4; mi++) {
                const int rm = wm + 16 * mi;
                a[mi][0] = ld_h2(&As[s][rm + g][kc]);
                a[mi][1] = ld_h2(&As[s][rm + g + 8][kc]);
                a[mi][2] = ld_h2(&As[s][rm + g][kc + 8]);
                a[mi][3] = ld_h2(&As[s][rm + g + 8][kc + 8]);
            }
            #pragma unroll
            for (int ni = 0; ni < 8; ni++) {
                const uint32_t b0 = ld_h2(&Bs[s][wn + 8 * ni + g][kc]);
                const uint32_t b1 = ld_h2(&Bs[s][wn + 8 * ni + g][kc + 8]);
                #pragma unroll
                for (int mi = 0; mi < 4; mi++)
                    mma_f16(acc[mi][ni], a[mi][0], a[mi][1], a[mi][2], a[mi][3], b0, b1);
            }
        }
        __syncthreads();
    }

    // epilogue: c0,c1 at (r0, col..col+1); c2,c3 at (r0+8, ...)
    #pragma unroll
    for (int mi = 0; mi < 4; mi++) {
        const int r0 = bm + wm + mi * 16 + g;
        #pragma unroll
        for (int ni = 0; ni < 8; ni++) {
            const int col = bn + wn + ni * 8 + t4 * 2;
            const float b0 = bias[col], b1 = bias[col + 1];
            float v[4];
            v[0] = acc[mi][ni][0] + b0;
            v[1] = acc[mi][ni][1] + b1;
            v[2] = acc[mi][ni][2] + b0;
            v[3] = acc[mi][ni][3] + b1;
            if (EPI == EPI_GELU) {
                #pragma unroll
                for (int c = 0; c < 4; c++)
                    v[c] = 0.5f * v[c] * (1.0f + erff(v[c] * 0.70710678118654752f));
            }
            if (EPI == EPI_RES) {
                const float2 r4a = *(const float2*)(R + (size_t)r0 * N + col);
                const float2 r4b = *(const float2*)(R + (size_t)(r0 + 8) * N + col);
                v[0] += r4a.x; v[1] += r4a.y;
                v[2] += r4b.x; v[3] += r4b.y;
            }
            if (OUTH) {
                *(__half2*)(Ch + (size_t)r0 * N + col)       = __floats2half2_rn(v[0], v[1]);
                *(__half2*)(Ch + (size_t)(r0 + 8) * N + col) = __floats2half2_rn(v[2], v[3]);
            } else {
                *(float2*)(Cf + (size_t)r0 * N + col)       = make_float2(v[0], v[1]);
                *(float2*)(Cf + (size_t)(r0 + 8) * N + col) = make_float2(v[2], v[3]);
            }
        }
    }
}

// ---------------- Flash attention, fp16 m16n8k16 -----------------------------
// Block: 128 queries x one (b,h); 8 warps x 16 q-rows; 64-key tiles.
__global__ void __launch_bounds__(256, 2) attn_h_kernel(__half* __restrict__ out)
{
    __shared__ __align__(16) __half Ks[2][64][40];   // [key][d]
    __shared__ __align__(16) __half Vt[2][32][72];   // [d][key]
    __shared__ __half Ps[8][16][72];                 // warp-private [q][key]

    const int b = blockIdx.z, h = blockIdx.y, q0 = blockIdx.x * 128;
    const int tid = threadIdx.x;
    const int warp = tid >> 5, lane = tid & 31;
    const int g = lane >> 2, t4 = lane & 3;
    const int wq = warp * 16;

    const float scale = 0.17677669529663687f;  // 1/sqrt(32)

    // staging maps
    const int kkey = tid >> 2, kch = (tid & 3) * 8;   // K: 64 keys x 4 chunks
    const int vd = tid >> 3, vch = (tid & 7) * 8;     // Vt: 32 d x 8 chunks

    // prologue: stage tile 0
    {
        const __half* kp = g_qkv + (size_t)(b * SEQ + kkey) * (3 * DIM)
                           + DIM + h * HD + kch;
        cp16(smem_u32(&Ks[0][kkey][kch]), kp);
        const __half* vp = g_vt + ((size_t)(b * HEADS + h) * HD + vd) * SEQ + vch;
        cp16(smem_u32(&Vt[0][vd][vch]), vp);
    }
    cp_commit();

    // Q fragments (held in regs): raw fp16 q (scale applied post-mma)
    uint32_t qf[2][4];
    {
        const __half* q0p = g_qkv + (size_t)(b * SEQ + q0 + wq + g) * (3 * DIM) + h * HD;
        const __half* q1p = q0p + 8 * (3 * DIM);
        #pragma unroll
        for (int ks = 0; ks < 2; ks++) {
            const int kc = 16 * ks + 2 * t4;
            qf[ks][0] = ld_h2(q0p + kc);
            qf[ks][1] = ld_h2(q1p + kc);
            qf[ks][2] = ld_h2(q0p + kc + 8);
            qf[ks][3] = ld_h2(q1p + kc + 8);
        }
    }

    float m0 = -1e30f, m1 = -1e30f, li0 = 0.0f, li1 = 0.0f;
    float acc_o[4][4];
    #pragma unroll
    for (int ni = 0; ni < 4; ni++)
        #pragma unroll
        for (int c = 0; c < 4; c++) acc_o[ni][c] = 0.0f;

    const float* bias0 = g_bias + ((size_t)h * SEQ + q0 + wq + g) * SEQ;
    const float* bias1 = bias0 + 8 * SEQ;

    for (int it = 0; it < SEQ / 64; it++) {
        const int s = it & 1;
        const int k0 = it * 64;
        if (it + 1 < SEQ / 64) {
            const int sn = s ^ 1;
            const __half* kp = g_qkv + (size_t)(b * SEQ + k0 + 64 + kkey) * (3 * DIM)
                               + DIM + h * HD + kch;
            cp16(smem_u32(&Ks[sn][kkey][kch]), kp);
            const __half* vp = g_vt + ((size_t)(b * HEADS + h) * HD + vd) * SEQ
                               + k0 + 64 + vch;
            cp16(smem_u32(&Vt[sn][vd][vch]), vp);
            cp_commit();
            cp_wait<1>();
        } else {
            cp_wait<0>();
        }
        __syncthreads();

        // ---- S = Q @ K^T  (raw, scaled below) ----
        float sacc[8][4];
        #pragma unroll
        for (int ni = 0; ni < 8; ni++)
            #pragma unroll
            for (int c = 0; c < 4; c++) sacc[ni][c] = 0.0f;
        #pragma unroll
        for (int ks = 0; ks < 2; ks++) {
            const int kc = 16 * ks + 2 * t4;
            #pragma unroll
            for (int ni = 0; ni < 8; ni++) {
                const uint32_t b0 = ld_h2(&Ks[s][ni * 8 + g][kc]);
                const uint32_t b1 = ld_h2(&Ks[s][ni * 8 + g][kc + 8]);
                mma_f16(sacc[ni], qf[ks][0], qf[ks][1], qf[ks][2], qf[ks][3], b0, b1);
            }
        }
        // ---- scale + bias ----
        #pragma unroll
        for (int ni = 0; ni < 8; ni++) {
            const int col = k0 + ni * 8 + t4 * 2;
            const float2 bv0 = *(const float2*)(bias0 + col);
            const float2 bv1 = *(const float2*)(bias1 + col);
            sacc[ni][0] = fmaf(sacc[ni][0], scale, bv0.x);
            sacc[ni][1] = fmaf(sacc[ni][1], scale, bv0.y);
            sacc[ni][2] = fmaf(sacc[ni][2], scale, bv1.x);
            sacc[ni][3] = fmaf(sacc[ni][3], scale, bv1.y);
        }

        // ---- online softmax ----
        float vmax0 = -1e30f, vmax1 = -1e30f;
        #pragma unroll
        for (int ni = 0; ni < 8; ni++) {
            vmax0 = fmaxf(vmax0, fmaxf(sacc[ni][0], sacc[ni][1]));
            vmax1 = fmaxf(vmax1, fmaxf(sacc[ni][2], sacc[ni][3]));
        }
        #pragma unroll
        for (int o = 1; o <= 2; o <<= 1) {
            vmax0 = fmaxf(vmax0, __shfl_xor_sync(0xffffffffu, vmax0, o));
            vmax1 = fmaxf(vmax1, __shfl_xor_sync(0xffffffffu, vmax1, o));
        }
        const float nm0 = fmaxf(m0, vmax0);
        const float nm1 = fmaxf(m1, vmax1);
        const float corr0 = __expf(m0 - nm0);
        const float corr1 = __expf(m1 - nm1);
        m0 = nm0; m1 = nm1;
        float rs0 = 0.0f, rs1 = 0.0f;

        __syncwarp();
        #pragma unroll
        for (int ni = 0; ni < 8; ni++) {
            const float p0 = __expf(sacc[ni][0] - m0);
            const float p1 = __expf(sacc[ni][1] - m0);
            const float p2 = __expf(sacc[ni][2] - m1);
            const float p3 = __expf(sacc[ni][3] - m1);
            rs0 += p0 + p1; rs1 += p2 + p3;
            const int col = ni * 8 + t4 * 2;
            *(__half2*)&Ps[warp][g][col]     = __floats2half2_rn(p0, p1);
            *(__half2*)&Ps[warp][g + 8][col] = __floats2half2_rn(p2, p3);
        }
        li0 = li0 * corr0 + rs0;
        li1 = li1 * corr1 + rs1;
        #pragma unroll
        for (int ni = 0; ni < 4; ni++) {
            acc_o[ni][0] *= corr0; acc_o[ni][1] *= corr0;
            acc_o[ni][2] *= corr1; acc_o[ni][3] *= corr1;
        }
        __syncwarp();

        // ---- O += P @ V  (K=64 = 4 ksteps; N=32 = 4 n-tiles) ----
        #pragma unroll
        for (int ks = 0; ks < 4; ks++) {
            const int kc = 16 * ks + 2 * t4;
            const uint32_t a0 = ld_h2(&Ps[warp][g][kc]);
            const uint32_t a1 = ld_h2(&Ps[warp][g + 8][kc]);
            const uint32_t a2 = ld_h2(&Ps[warp][g][kc + 8]);
            const uint32_t a3 = ld_h2(&Ps[warp][g + 8][kc + 8]);
            #pragma unroll
            for (int ni = 0; ni < 4; ni++) {
                const uint32_t b0 = ld_h2(&Vt[s][ni * 8 + g][kc]);
                const uint32_t b1 = ld_h2(&Vt[s][ni * 8 + g][kc + 8]);
                mma_f16(acc_o[ni], a0, a1, a2, a3, b0, b1);
            }
        }
        __syncthreads();
    }

    // ---- finalize ----
    #pragma unroll
    for (int o = 1; o <= 2; o <<= 1) {
        li0 += __shfl_xor_sync(0xffffffffu, li0, o);
        li1 += __shfl_xor_sync(0xffffffffu, li1, o);
    }
    const float inv0 = 1.0f / li0;
    const float inv1 = 1.0f / li1;
    __half* o0p = out + (size_t)(b * SEQ + q0 + wq + g) * DIM + h * HD;
    __half* o1p = o0p + 8 * DIM;
    #pragma unroll
    for (int ni = 0; ni < 4; ni++) {
        const int col = ni * 8 + t4 * 2;
        *(__half2*)(o0p + col) = __floats2half2_rn(acc_o[ni][0] * inv0,
                                                   acc_o[ni][1] * inv0);
        *(__half2*)(o1p + col) = __floats2half2_rn(acc_o[ni][2] * inv1,
                                                   acc_o[ni][3] * inv1);
    }
}

// ---------------- launch -----------------------------------------------------
extern "C" void kernel_launch(void* const* d_in, const int* in_sizes, int n_in,
                              void* d_out, int out_size)
{
    const float* x      = (const float*)d_in[0];
    const int*   rel    = (const int*)  d_in[1];
    const float* table  = (const float*)d_in[2];
    const float* qkv_w  = (const float*)d_in[3];
    const float* qkv_b  = (const float*)d_in[4];
    const float* proj_w = (const float*)d_in[5];
    const float* proj_b = (const float*)d_in[6];
    const float* n1_g   = (const float*)d_in[7];
    const float* n1_b   = (const float*)d_in[8];
    const float* n2_g   = (const float*)d_in[9];
    const float* n2_b   = (const float*)d_in[10];
    const float* fc1_w  = (const float*)d_in[11];
    const float* fc1_b  = (const float*)d_in[12];
    const float* fc2_w  = (const float*)d_in[13];
    const float* fc2_b  = (const float*)d_in[14];
    float* out = (float*)d_out;

    __half *h, *qkv, *attnout, *mlp1, *w;
    float *xres;
    cudaGetSymbolAddress((void**)&h,       g_h);
    cudaGetSymbolAddress((void**)&qkv,     g_qkv);
    cudaGetSymbolAddress((void**)&attnout, g_attnout);
    cudaGetSymbolAddress((void**)&xres,    g_xres);
    cudaGetSymbolAddress((void**)&mlp1,    g_mlp1);
    cudaGetSymbolAddress((void**)&w,       g_w);

    dim3 tb(32, 8);
    // 0. transpose + convert weights -> fp16 [N][K]
    cvt_t_kernel<<<dim3(48, 16), tb>>>(qkv_w,  w + W_QKV,  DIM,  3 * DIM);
    cvt_t_kernel<<<dim3(16, 16), tb>>>(proj_w, w + W_PROJ, DIM,  DIM);
    cvt_t_kernel<<<dim3(64, 16), tb>>>(fc1_w,  w + W_FC1,  DIM,  MLPH);
    cvt_t_kernel<<<dim3(16, 64), tb>>>(fc2_w,  w + W_FC2,  MLPH, DIM);
    // 1. h = LN1(x)
    ln_kernel<<<MROWS, 128>>>(x, n1_g, n1_b, h);
    // 2. qkv = fp16(h @ qkv_w + qkv_b)
    gemm_h<EPI_BIAS, 1><<<dim3(12, 64), 128>>>(h, w + W_QKV, qkv_b, nullptr,
                                               nullptr, qkv, MROWS, 3 * DIM, DIM);
    // 3. bias expand + V transpose
    bias_expand_kernel<<<(HEADS * SEQ * SEQ) / 256, 256>>>(rel, table);
    vt_kernel<<<dim3(SEQ / 32, HEADS, BATCH), tb>>>();
    // 4. flash attention -> fp16 [B, L, C]
    attn_h_kernel<<<dim3(8, HEADS, BATCH), 256>>>(attnout);
    // 5. xres = x + attnout @ proj_w + proj_b  (fp32)
    gemm_h<EPI_RES, 0><<<dim3(4, 64), 128>>>(attnout, w + W_PROJ, proj_b, x,
                                             xres, nullptr, MROWS, DIM, DIM);
    // 6. h = LN2(xres)
    ln_kernel<<<MROWS, 128>>>(xres, n2_g, n2_b, h);
    // 7. mlp1 = fp16(gelu(h @ fc1_w + fc1_b))
    gemm_h<EPI_GELU, 1><<<dim3(16, 64), 128>>>(h, w + W_FC1, fc1_b, nullptr,
                                               nullptr, mlp1, MROWS, MLPH, DIM);
    // 8. out = xres + mlp1 @ fc2_w + fc2_b  (fp32)
    gemm_h<EPI_RES, 0><<<dim3(4, 64), 128>>>(mlp1, w + W_FC2, fc2_b, xres,
                                             out, nullptr, MROWS, DIM, MLPH);
}

// round 11
// speedup vs baseline: 1.8820x; 1.2730x over previous
#include <cuda_runtime.h>
#include <cuda_fp16.h>
#include <math.h>
#include <stdint.h>

#define BATCH 8
#define SEQ 1024
#define DIM 512
#define HEADS 16
#define HD 32
#define MROWS (BATCH*SEQ)   /* 8192 */
#define MLPH 2048
#define TBLN 3969           /* (2*32-1)^2 */

// ---------------- scratch (device globals; no allocations allowed) ----------
__device__ __align__(256) __half g_h[MROWS * DIM];         // LN out (fp16)
__device__ __align__(256) __half g_qkv[MROWS * 3 * DIM];   // q|k|v (fp16)
__device__ __align__(256) __half g_vt[BATCH * HEADS * HD * SEQ]; // V^T per (b,h)
__device__ __align__(256) __half g_attnout[MROWS * DIM];   // attention out (fp16)
__device__ __align__(256) __half g_mlp1[MROWS * MLPH];     // gelu(fc1) (fp16)
__device__ __align__(256) __half g_w[3145728];             // [N][K] fp16 weights
__device__ float g_xres[MROWS * DIM];                      // x + proj(attn) fp32

#define W_QKV  0
#define W_PROJ 786432
#define W_FC1  1048576
#define W_FC2  2097152

// ---------------- helpers ----------------------------------------------------
__device__ __forceinline__ void mma_f16(float* c, uint32_t a0, uint32_t a1,
                                        uint32_t a2, uint32_t a3,
                                        uint32_t b0, uint32_t b1) {
    asm volatile(
        "mma.sync.aligned.m16n8k16.row.col.f32.f16.f16.f32 "
        "{%0,%1,%2,%3}, {%4,%5,%6,%7}, {%8,%9}, {%0,%1,%2,%3};"
        : "+f"(c[0]), "+f"(c[1]), "+f"(c[2]), "+f"(c[3])
        : "r"(a0), "r"(a1), "r"(a2), "r"(a3), "r"(b0), "r"(b1));
}

__device__ __forceinline__ void cp16(uint32_t s, const void* g) {
    asm volatile("cp.async.cg.shared.global [%0], [%1], 16;\n" :: "r"(s), "l"(g));
}
__device__ __forceinline__ void cp_commit() {
    asm volatile("cp.async.commit_group;\n");
}
template <int N> __device__ __forceinline__ void cp_wait() {
    asm volatile("cp.async.wait_group %0;\n" :: "n"(N));
}
__device__ __forceinline__ uint32_t smem_u32(const void* p) {
    uint32_t a;
    asm("{ .reg .u64 t; cvta.to.shared.u64 t, %1; cvt.u32.u64 %0, t; }"
        : "=r"(a) : "l"(p));
    return a;
}
__device__ __forceinline__ uint32_t ld_h2(const __half* p) {
    return *(const uint32_t*)p;
}

// ---------------- weight transpose + fp16 convert ----------------------------
// in: [K][N] fp32 row-major.  out: [N][K] fp16
__global__ void __launch_bounds__(256) cvt_t_kernel(const float* __restrict__ in,
                                                    __half* __restrict__ out,
                                                    int K, int N)
{
    __shared__ float tile[32][33];
    const int bk = blockIdx.y * 32, bn = blockIdx.x * 32;
    const int tx = threadIdx.x, ty = threadIdx.y;
    #pragma unroll
    for (int i = 0; i < 4; i++)
        tile[ty + 8 * i][tx] = in[(size_t)(bk + ty + 8 * i) * N + bn + tx];
    __syncthreads();
    #pragma unroll
    for (int i = 0; i < 4; i++) {
        const int n = ty + 8 * i;
        out[(size_t)(bn + n) * K + bk + tx] = __float2half_rn(tile[tx][n]);
    }
}

// ---------------- V transpose: g_qkv v-section -> Vt[b][h][d][seq] -----------
__global__ void __launch_bounds__(256) vt_kernel()
{
    __shared__ __half tile[32][34];
    const int m0 = blockIdx.x * 32, h = blockIdx.y, b = blockIdx.z;
    const int tx = threadIdx.x, ty = threadIdx.y;
    const __half* in = g_qkv + (size_t)(b * SEQ) * (3 * DIM) + 2 * DIM + h * HD;
    #pragma unroll
    for (int i = 0; i < 4; i++)
        tile[ty + 8 * i][tx] = in[(size_t)(m0 + ty + 8 * i) * (3 * DIM) + tx];
    __syncthreads();
    __half* out = g_vt + ((size_t)(b * HEADS + h) * HD) * SEQ + m0;
    #pragma unroll
    for (int i = 0; i < 4; i++) {
        const int d = ty + 8 * i;
        out[(size_t)d * SEQ + tx] = tile[tx][d];
    }
}

// ---------------- LayerNorm (fp16 output) ------------------------------------
__global__ void __launch_bounds__(128) ln_kernel(const float* __restrict__ x,
                                                 const float* __restrict__ g,
                                                 const float* __restrict__ b,
                                                 __half* __restrict__ out)
{
    const int row = blockIdx.x;
    const int t = threadIdx.x;
    const float4 v = ((const float4*)(x + (size_t)row * DIM))[t];
    float s  = v.x + v.y + v.z + v.w;
    float s2 = v.x*v.x + v.y*v.y + v.z*v.z + v.w*v.w;
    #pragma unroll
    for (int o = 16; o > 0; o >>= 1) {
        s  += __shfl_xor_sync(0xffffffffu, s,  o);
        s2 += __shfl_xor_sync(0xffffffffu, s2, o);
    }
    __shared__ float rs[4], rs2[4];
    if ((t & 31) == 0) { rs[t >> 5] = s; rs2[t >> 5] = s2; }
    __syncthreads();
    s  = rs[0] + rs[1] + rs[2] + rs[3];
    s2 = rs2[0] + rs2[1] + rs2[2] + rs2[3];
    const float mean = s * (1.0f / DIM);
    const float var  = s2 * (1.0f / DIM) - mean * mean;
    const float inv  = rsqrtf(var + 1e-5f);
    const float4 gg = ((const float4*)g)[t];
    const float4 bb = ((const float4*)b)[t];
    __half2* op = (__half2*)(out + (size_t)row * DIM + 4 * t);
    op[0] = __floats2half2_rn((v.x - mean) * inv * gg.x + bb.x,
                              (v.y - mean) * inv * gg.y + bb.y);
    op[1] = __floats2half2_rn((v.z - mean) * inv * gg.z + bb.z,
                              (v.w - mean) * inv * gg.w + bb.w);
}

// ---------------- fp16 tensor-core GEMM, 3-stage cp.async pipeline -----------
// C[M,N] = epilogue(A[M,K] @ Wt[N,K]^T + bias [, R])
// 128x128 block, BK=32, 128 thr = 4 warps (2x2), warp tile 64x64, m16n8k16.
enum { EPI_BIAS = 0, EPI_GELU = 1, EPI_RES = 2 };

template <int EPI, int OUTH>
__global__ void __launch_bounds__(128, 2) gemm_h(const __half* __restrict__ A,
                                                 const __half* __restrict__ Wt,
                                                 const float* __restrict__ bias,
                                                 const float* __restrict__ R,
                                                 float* __restrict__ Cf,
                                                 __half* __restrict__ Ch,
                                                 int M, int N, int K)
{
    __shared__ __align__(16) __half As[3][128][40];   // [m][k]
    __shared__ __align__(16) __half Bs[3][128][40];   // [n][k]

    const int bm = blockIdx.y * 128, bn = blockIdx.x * 128;
    const int tid = threadIdx.x;
    const int warp = tid >> 5, lane = tid & 31;
    const int wm = (warp & 1) * 64, wn = (warp >> 1) * 64;
    const int g = lane >> 2, t4 = lane & 3;

    const int srow = tid >> 2, sch = (tid & 3) * 8;

    float acc[4][8][4];
    #pragma unroll
    for (int mi = 0; mi < 4; mi++)
        #pragma unroll
        for (int ni = 0; ni < 8; ni++)
            #pragma unroll
            for (int c = 0; c < 4; c++) acc[mi][ni][c] = 0.0f;

    const int nk = K >> 5;

    // prologue: stages 0, 1
    #pragma unroll
    for (int st = 0; st < 2; st++) {
        const int k0 = st * 32;
        #pragma unroll
        for (int i = 0; i < 4; i++) {
            const int r = srow + i * 32;
            cp16(smem_u32(&As[st][r][sch]), A + (size_t)(bm + r) * K + k0 + sch);
            cp16(smem_u32(&Bs[st][r][sch]), Wt + (size_t)(bn + r) * K + k0 + sch);
        }
        cp_commit();
    }

    int s = 0;
    for (int kt = 0; kt < nk; kt++) {
        if (kt + 2 < nk) {
            const int k0 = (kt + 2) * 32;
            const int sn = (s + 2) % 3;
            #pragma unroll
            for (int i = 0; i < 4; i++) {
                const int r = srow + i * 32;
                cp16(smem_u32(&As[sn][r][sch]), A + (size_t)(bm + r) * K + k0 + sch);
                cp16(smem_u32(&Bs[sn][r][sch]), Wt + (size_t)(bn + r) * K + k0 + sch);
            }
            cp_commit();
            cp_wait<2>();
        } else if (kt + 1 < nk) {
            cp_wait<1>();
        } else {
            cp_wait<0>();
        }
        __syncthreads();

        #pragma unroll
        for (int ks = 0; ks < 2; ks++) {
            const int kc = 16 * ks + 2 * t4;
            uint32_t a[4][4];
            #pragma unroll
            for (int mi = 0; mi < 4; mi++) {
                const int rm = wm + 16 * mi;
                a[mi][0] = ld_h2(&As[s][rm + g][kc]);
                a[mi][1] = ld_h2(&As[s][rm + g + 8][kc]);
                a[mi][2] = ld_h2(&As[s][rm + g][kc + 8]);
                a[mi][3] = ld_h2(&As[s][rm + g + 8][kc + 8]);
            }
            #pragma unroll
            for (int ni = 0; ni < 8; ni++) {
                const uint32_t b0 = ld_h2(&Bs[s][wn + 8 * ni + g][kc]);
                const uint32_t b1 = ld_h2(&Bs[s][wn + 8 * ni + g][kc + 8]);
                #pragma unroll
                for (int mi = 0; mi < 4; mi++)
                    mma_f16(acc[mi][ni], a[mi][0], a[mi][1], a[mi][2], a[mi][3], b0, b1);
            }
        }
        __syncthreads();
        s = (s + 1) % 3;
    }

    // epilogue
    #pragma unroll
    for (int mi = 0; mi < 4; mi++) {
        const int r0 = bm + wm + mi * 16 + g;
        #pragma unroll
        for (int ni = 0; ni < 8; ni++) {
            const int col = bn + wn + ni * 8 + t4 * 2;
            const float b0 = bias[col], b1 = bias[col + 1];
            float v[4];
            v[0] = acc[mi][ni][0] + b0;
            v[1] = acc[mi][ni][1] + b1;
            v[2] = acc[mi][ni][2] + b0;
            v[3] = acc[mi][ni][3] + b1;
            if (EPI == EPI_GELU) {
                #pragma unroll
                for (int c = 0; c < 4; c++)
                    v[c] = 0.5f * v[c] * (1.0f + erff(v[c] * 0.70710678118654752f));
            }
            if (EPI == EPI_RES) {
                const float2 r4a = *(const float2*)(R + (size_t)r0 * N + col);
                const float2 r4b = *(const float2*)(R + (size_t)(r0 + 8) * N + col);
                v[0] += r4a.x; v[1] += r4a.y;
                v[2] += r4b.x; v[3] += r4b.y;
            }
            if (OUTH) {
                *(__half2*)(Ch + (size_t)r0 * N + col)       = __floats2half2_rn(v[0], v[1]);
                *(__half2*)(Ch + (size_t)(r0 + 8) * N + col) = __floats2half2_rn(v[2], v[3]);
            } else {
                *(float2*)(Cf + (size_t)r0 * N + col)       = make_float2(v[0], v[1]);
                *(float2*)(Cf + (size_t)(r0 + 8) * N + col) = make_float2(v[2], v[3]);
            }
        }
    }
}

// ---------------- Flash attention, fp16, closed-form smem bias ---------------
// Block: 128 queries x one (b,h); 8 warps x 16 q-rows; 64-key tiles.
__global__ void __launch_bounds__(256, 2) attn_h_kernel(const float* __restrict__ table,
                                                        __half* __restrict__ out)
{
    __shared__ __align__(16) __half Ks[2][64][40];   // [key][d]
    __shared__ __align__(16) __half Vt[2][32][72];   // [d][key]
    __shared__ __half Ps[8][16][72];                 // warp-private [q][key]
    __shared__ float tbl[TBLN];                      // per-head bias table column

    const int b = blockIdx.z, h = blockIdx.y, q0 = blockIdx.x * 128;
    const int tid = threadIdx.x;
    const int warp = tid >> 5, lane = tid & 31;
    const int g = lane >> 2, t4 = lane & 3;
    const int wq = warp * 16;

    const float scale = 0.17677669529663687f;  // 1/sqrt(32)

    // staging maps
    const int kkey = tid >> 2, kch = (tid & 3) * 8;   // K: 64 keys x 4 chunks
    const int vd = tid >> 3, vch = (tid & 7) * 8;     // Vt: 32 d x 8 chunks

    // prologue: stage tile 0 (issue before table gather)
    {
        const __half* kp = g_qkv + (size_t)(b * SEQ + kkey) * (3 * DIM)
                           + DIM + h * HD + kch;
        cp16(smem_u32(&Ks[0][kkey][kch]), kp);
        const __half* vp = g_vt + ((size_t)(b * HEADS + h) * HD + vd) * SEQ + vch;
        cp16(smem_u32(&Vt[0][vd][vch]), vp);
    }
    cp_commit();

    // per-head bias table column -> smem
    for (int i = tid; i < TBLN; i += 256) tbl[i] = table[i * HEADS + h];

    // Q fragments (raw fp16; scale folded into post-mma FFMA)
    uint32_t qf[2][4];
    {
        const __half* q0p = g_qkv + (size_t)(b * SEQ + q0 + wq + g) * (3 * DIM) + h * HD;
        const __half* q1p = q0p + 8 * (3 * DIM);
        #pragma unroll
        for (int ks = 0; ks < 2; ks++) {
            const int kc = 16 * ks + 2 * t4;
            qf[ks][0] = ld_h2(q0p + kc);
            qf[ks][1] = ld_h2(q1p + kc);
            qf[ks][2] = ld_h2(q0p + kc + 8);
            qf[ks][3] = ld_h2(q1p + kc + 8);
        }
    }

    // rel-index bases: ri = (ly - my)*63 + (lx - mx) + 1984
    const int l0 = q0 + wq + g, l1 = l0 + 8;
    const int Cb0 = (l0 >> 5) * 63 + (l0 & 31) + 1984;
    const int Cb1 = (l1 >> 5) * 63 + (l1 & 31) + 1984;

    float m0 = -1e30f, m1 = -1e30f, li0 = 0.0f, li1 = 0.0f;
    float acc_o[4][4];
    #pragma unroll
    for (int ni = 0; ni < 4; ni++)
        #pragma unroll
        for (int c = 0; c < 4; c++) acc_o[ni][c] = 0.0f;

    for (int it = 0; it < SEQ / 64; it++) {
        const int s = it & 1;
        const int k0 = it * 64;
        if (it + 1 < SEQ / 64) {
            const int sn = s ^ 1;
            const __half* kp = g_qkv + (size_t)(b * SEQ + k0 + 64 + kkey) * (3 * DIM)
                               + DIM + h * HD + kch;
            cp16(smem_u32(&Ks[sn][kkey][kch]), kp);
            const __half* vp = g_vt + ((size_t)(b * HEADS + h) * HD + vd) * SEQ
                               + k0 + 64 + vch;
            cp16(smem_u32(&Vt[sn][vd][vch]), vp);
            cp_commit();
            cp_wait<1>();
        } else {
            cp_wait<0>();
        }
        __syncthreads();

        // ---- S = Q @ K^T  (raw, scale+bias fused below) ----
        float sacc[8][4];
        #pragma unroll
        for (int ni = 0; ni < 8; ni++)
            #pragma unroll
            for (int c = 0; c < 4; c++) sacc[ni][c] = 0.0f;
        #pragma unroll
        for (int ks = 0; ks < 2; ks++) {
            const int kc = 16 * ks + 2 * t4;
            #pragma unroll
            for (int ni = 0; ni < 8; ni++) {
                const uint32_t b0 = ld_h2(&Ks[s][ni * 8 + g][kc]);
                const uint32_t b1 = ld_h2(&Ks[s][ni * 8 + g][kc + 8]);
                mma_f16(sacc[ni], qf[ks][0], qf[ks][1], qf[ks][2], qf[ks][3], b0, b1);
            }
        }
        // ---- scale + rel-pos bias from smem table ----
        {
            const int base0 = Cb0 - (k0 >> 5) * 63;
            const int base1 = Cb1 - (k0 >> 5) * 63;
            #pragma unroll
            for (int ni = 0; ni < 8; ni++) {
                const int off = (ni >> 2) * 63 + 8 * (ni & 3) + 2 * t4;
                sacc[ni][0] = fmaf(sacc[ni][0], scale, tbl[base0 - off]);
                sacc[ni][1] = fmaf(sacc[ni][1], scale, tbl[base0 - off - 1]);
                sacc[ni][2] = fmaf(sacc[ni][2], scale, tbl[base1 - off]);
                sacc[ni][3] = fmaf(sacc[ni][3], scale, tbl[base1 - off - 1]);
            }
        }

        // ---- online softmax ----
        float vmax0 = -1e30f, vmax1 = -1e30f;
        #pragma unroll
        for (int ni = 0; ni < 8; ni++) {
            vmax0 = fmaxf(vmax0, fmaxf(sacc[ni][0], sacc[ni][1]));
            vmax1 = fmaxf(vmax1, fmaxf(sacc[ni][2], sacc[ni][3]));
        }
        #pragma unroll
        for (int o = 1; o <= 2; o <<= 1) {
            vmax0 = fmaxf(vmax0, __shfl_xor_sync(0xffffffffu, vmax0, o));
            vmax1 = fmaxf(vmax1, __shfl_xor_sync(0xffffffffu, vmax1, o));
        }
        const float nm0 = fmaxf(m0, vmax0);
        const float nm1 = fmaxf(m1, vmax1);
        const float corr0 = __expf(m0 - nm0);
        const float corr1 = __expf(m1 - nm1);
        m0 = nm0; m1 = nm1;
        float rs0 = 0.0f, rs1 = 0.0f;

        __syncwarp();
        #pragma unroll
        for (int ni = 0; ni < 8; ni++) {
            const float p0 = __expf(sacc[ni][0] - m0);
            const float p1 = __expf(sacc[ni][1] - m0);
            const float p2 = __expf(sacc[ni][2] - m1);
            const float p3 = __expf(sacc[ni][3] - m1);
            rs0 += p0 + p1; rs1 += p2 + p3;
            const int col = ni * 8 + t4 * 2;
            *(__half2*)&Ps[warp][g][col]     = __floats2half2_rn(p0, p1);
            *(__half2*)&Ps[warp][g + 8][col] = __floats2half2_rn(p2, p3);
        }
        li0 = li0 * corr0 + rs0;
        li1 = li1 * corr1 + rs1;
        #pragma unroll
        for (int ni = 0; ni < 4; ni++) {
            acc_o[ni][0] *= corr0; acc_o[ni][1] *= corr0;
            acc_o[ni][2] *= corr1; acc_o[ni][3] *= corr1;
        }
        __syncwarp();

        // ---- O += P @ V ----
        #pragma unroll
        for (int ks = 0; ks < 4; ks++) {
            const int kc = 16 * ks + 2 * t4;
            const uint32_t a0 = ld_h2(&Ps[warp][g][kc]);
            const uint32_t a1 = ld_h2(&Ps[warp][g + 8][kc]);
            const uint32_t a2 = ld_h2(&Ps[warp][g][kc + 8]);
            const uint32_t a3 = ld_h2(&Ps[warp][g + 8][kc + 8]);
            #pragma unroll
            for (int ni = 0; ni < 4; ni++) {
                const uint32_t b0 = ld_h2(&Vt[s][ni * 8 + g][kc]);
                const uint32_t b1 = ld_h2(&Vt[s][ni * 8 + g][kc + 8]);
                mma_f16(acc_o[ni], a0, a1, a2, a3, b0, b1);
            }
        }
        __syncthreads();
    }

    // ---- finalize ----
    #pragma unroll
    for (int o = 1; o <= 2; o <<= 1) {
        li0 += __shfl_xor_sync(0xffffffffu, li0, o);
        li1 += __shfl_xor_sync(0xffffffffu, li1, o);
    }
    const float inv0 = 1.0f / li0;
    const float inv1 = 1.0f / li1;
    __half* o0p = out + (size_t)(b * SEQ + q0 + wq + g) * DIM + h * HD;
    __half* o1p = o0p + 8 * DIM;
    #pragma unroll
    for (int ni = 0; ni < 4; ni++) {
        const int col = ni * 8 + t4 * 2;
        *(__half2*)(o0p + col) = __floats2half2_rn(acc_o[ni][0] * inv0,
                                                   acc_o[ni][1] * inv0);
        *(__half2*)(o1p + col) = __floats2half2_rn(acc_o[ni][2] * inv1,
                                                   acc_o[ni][3] * inv1);
    }
}

// ---------------- launch -----------------------------------------------------
extern "C" void kernel_launch(void* const* d_in, const int* in_sizes, int n_in,
                              void* d_out, int out_size)
{
    const float* x      = (const float*)d_in[0];
    const float* table  = (const float*)d_in[2];
    const float* qkv_w  = (const float*)d_in[3];
    const float* qkv_b  = (const float*)d_in[4];
    const float* proj_w = (const float*)d_in[5];
    const float* proj_b = (const float*)d_in[6];
    const float* n1_g   = (const float*)d_in[7];
    const float* n1_b   = (const float*)d_in[8];
    const float* n2_g   = (const float*)d_in[9];
    const float* n2_b   = (const float*)d_in[10];
    const float* fc1_w  = (const float*)d_in[11];
    const float* fc1_b  = (const float*)d_in[12];
    const float* fc2_w  = (const float*)d_in[13];
    const float* fc2_b  = (const float*)d_in[14];
    float* out = (float*)d_out;

    __half *h, *qkv, *attnout, *mlp1, *w;
    float *xres;
    cudaGetSymbolAddress((void**)&h,       g_h);
    cudaGetSymbolAddress((void**)&qkv,     g_qkv);
    cudaGetSymbolAddress((void**)&attnout, g_attnout);
    cudaGetSymbolAddress((void**)&xres,    g_xres);
    cudaGetSymbolAddress((void**)&mlp1,    g_mlp1);
    cudaGetSymbolAddress((void**)&w,       g_w);

    dim3 tb(32, 8);
    // 0. transpose + convert weights -> fp16 [N][K]
    cvt_t_kernel<<<dim3(48, 16), tb>>>(qkv_w,  w + W_QKV,  DIM,  3 * DIM);
    cvt_t_kernel<<<dim3(16, 16), tb>>>(proj_w, w + W_PROJ, DIM,  DIM);
    cvt_t_kernel<<<dim3(64, 16), tb>>>(fc1_w,  w + W_FC1,  DIM,  MLPH);
    cvt_t_kernel<<<dim3(16, 64), tb>>>(fc2_w,  w + W_FC2,  MLPH, DIM);
    // 1. h = LN1(x)
    ln_kernel<<<MROWS, 128>>>(x, n1_g, n1_b, h);
    // 2. qkv = fp16(h @ qkv_w + qkv_b)
    gemm_h<EPI_BIAS, 1><<<dim3(12, 64), 128>>>(h, w + W_QKV, qkv_b, nullptr,
                                               nullptr, qkv, MROWS, 3 * DIM, DIM);
    // 3. V transpose
    vt_kernel<<<dim3(SEQ / 32, HEADS, BATCH), tb>>>();
    // 4. flash attention (closed-form bias) -> fp16 [B, L, C]
    attn_h_kernel<<<dim3(8, HEADS, BATCH), 256>>>(table, attnout);
    // 5. xres = x + attnout @ proj_w + proj_b  (fp32)
    gemm_h<EPI_RES, 0><<<dim3(4, 64), 128>>>(attnout, w + W_PROJ, proj_b, x,
                                             xres, nullptr, MROWS, DIM, DIM);
    // 6. h = LN2(xres)
    ln_kernel<<<MROWS, 128>>>(xres, n2_g, n2_b, h);
    // 7. mlp1 = fp16(gelu(h @ fc1_w + fc1_b))
    gemm_h<EPI_GELU, 1><<<dim3(16, 64), 128>>>(h, w + W_FC1, fc1_b, nullptr,
                                               nullptr, mlp1, MROWS, MLPH, DIM);
    // 8. out = xres + mlp1 @ fc2_w + fc2_b  (fp32)
    gemm_h<EPI_RES, 0><<<dim3(4, 64), 128>>>(mlp1, w + W_FC2, fc2_b, xres,
                                             out, nullptr, MROWS, DIM, MLPH);
}

// round 12
// speedup vs baseline: 1.9262x; 1.0235x over previous
#include <cuda_runtime.h>
#include <cuda_fp16.h>
#include <math.h>
#include <stdint.h>

#define BATCH 8
#define SEQ 1024
#define DIM 512
#define HEADS 16
#define HD 32
#define MROWS (BATCH*SEQ)   /* 8192 */
#define MLPH 2048
#define TBLN 3969           /* (2*32-1)^2 */

// ---------------- scratch (device globals; no allocations allowed) ----------
__device__ __align__(256) __half g_h[MROWS * DIM];         // LN out (fp16)
__device__ __align__(256) __half g_qkv[MROWS * 3 * DIM];   // q|k|v (fp16)
__device__ __align__(256) __half g_vt[BATCH * HEADS * HD * SEQ]; // V^T per (b,h)
__device__ __align__(256) __half g_attnout[MROWS * DIM];   // attention out (fp16)
__device__ __align__(256) __half g_mlp1[MROWS * MLPH];     // gelu(fc1) (fp16)
__device__ __align__(256) __half g_w[3145728];             // [N][K] fp16 weights
__device__ float g_xres[MROWS * DIM];                      // x + proj(attn) fp32

#define W_QKV  0
#define W_PROJ 786432
#define W_FC1  1048576
#define W_FC2  2097152

// ---------------- helpers ----------------------------------------------------
__device__ __forceinline__ void mma_f16(float* c, uint32_t a0, uint32_t a1,
                                        uint32_t a2, uint32_t a3,
                                        uint32_t b0, uint32_t b1) {
    asm volatile(
        "mma.sync.aligned.m16n8k16.row.col.f32.f16.f16.f32 "
        "{%0,%1,%2,%3}, {%4,%5,%6,%7}, {%8,%9}, {%0,%1,%2,%3};"
        : "+f"(c[0]), "+f"(c[1]), "+f"(c[2]), "+f"(c[3])
        : "r"(a0), "r"(a1), "r"(a2), "r"(a3), "r"(b0), "r"(b1));
}

__device__ __forceinline__ void cp16(uint32_t s, const void* g) {
    asm volatile("cp.async.cg.shared.global [%0], [%1], 16;\n" :: "r"(s), "l"(g));
}
__device__ __forceinline__ void cp_commit() {
    asm volatile("cp.async.commit_group;\n");
}
template <int N> __device__ __forceinline__ void cp_wait() {
    asm volatile("cp.async.wait_group %0;\n" :: "n"(N));
}
__device__ __forceinline__ uint32_t smem_u32(const void* p) {
    uint32_t a;
    asm("{ .reg .u64 t; cvta.to.shared.u64 t, %1; cvt.u32.u64 %0, t; }"
        : "=r"(a) : "l"(p));
    return a;
}
__device__ __forceinline__ uint32_t ld_h2(const __half* p) {
    return *(const uint32_t*)p;
}
__device__ __forceinline__ uint32_t pack_h2(float lo, float hi) {
    const __half2 h = __floats2half2_rn(lo, hi);
    return *(const uint32_t*)&h;
}

// ---------------- weight transpose + fp16 convert ----------------------------
// in: [K][N] fp32 row-major.  out: [N][K] fp16
__global__ void __launch_bounds__(256) cvt_t_kernel(const float* __restrict__ in,
                                                    __half* __restrict__ out,
                                                    int K, int N)
{
    __shared__ float tile[32][33];
    const int bk = blockIdx.y * 32, bn = blockIdx.x * 32;
    const int tx = threadIdx.x, ty = threadIdx.y;
    #pragma unroll
    for (int i = 0; i < 4; i++)
        tile[ty + 8 * i][tx] = in[(size_t)(bk + ty + 8 * i) * N + bn + tx];
    __syncthreads();
    #pragma unroll
    for (int i = 0; i < 4; i++) {
        const int n = ty + 8 * i;
        out[(size_t)(bn + n) * K + bk + tx] = __float2half_rn(tile[tx][n]);
    }
}

// ---------------- V transpose: g_qkv v-section -> Vt[b][h][d][seq] -----------
__global__ void __launch_bounds__(256) vt_kernel()
{
    __shared__ __half tile[32][34];
    const int m0 = blockIdx.x * 32, h = blockIdx.y, b = blockIdx.z;
    const int tx = threadIdx.x, ty = threadIdx.y;
    const __half* in = g_qkv + (size_t)(b * SEQ) * (3 * DIM) + 2 * DIM + h * HD;
    #pragma unroll
    for (int i = 0; i < 4; i++)
        tile[ty + 8 * i][tx] = in[(size_t)(m0 + ty + 8 * i) * (3 * DIM) + tx];
    __syncthreads();
    __half* out = g_vt + ((size_t)(b * HEADS + h) * HD) * SEQ + m0;
    #pragma unroll
    for (int i = 0; i < 4; i++) {
        const int d = ty + 8 * i;
        out[(size_t)d * SEQ + tx] = tile[tx][d];
    }
}

// ---------------- LayerNorm (fp16 output) ------------------------------------
__global__ void __launch_bounds__(128) ln_kernel(const float* __restrict__ x,
                                                 const float* __restrict__ g,
                                                 const float* __restrict__ b,
                                                 __half* __restrict__ out)
{
    const int row = blockIdx.x;
    const int t = threadIdx.x;
    const float4 v = ((const float4*)(x + (size_t)row * DIM))[t];
    float s  = v.x + v.y + v.z + v.w;
    float s2 = v.x*v.x + v.y*v.y + v.z*v.z + v.w*v.w;
    #pragma unroll
    for (int o = 16; o > 0; o >>= 1) {
        s  += __shfl_xor_sync(0xffffffffu, s,  o);
        s2 += __shfl_xor_sync(0xffffffffu, s2, o);
    }
    __shared__ float rs[4], rs2[4];
    if ((t & 31) == 0) { rs[t >> 5] = s; rs2[t >> 5] = s2; }
    __syncthreads();
    s  = rs[0] + rs[1] + rs[2] + rs[3];
    s2 = rs2[0] + rs2[1] + rs2[2] + rs2[3];
    const float mean = s * (1.0f / DIM);
    const float var  = s2 * (1.0f / DIM) - mean * mean;
    const float inv  = rsqrtf(var + 1e-5f);
    const float4 gg = ((const float4*)g)[t];
    const float4 bb = ((const float4*)b)[t];
    __half2* op = (__half2*)(out + (size_t)row * DIM + 4 * t);
    op[0] = __floats2half2_rn((v.x - mean) * inv * gg.x + bb.x,
                              (v.y - mean) * inv * gg.y + bb.y);
    op[1] = __floats2half2_rn((v.z - mean) * inv * gg.z + bb.z,
                              (v.w - mean) * inv * gg.w + bb.w);
}

// ---------------- fp16 tensor-core GEMM, 3-stage cp.async pipeline -----------
// C[M,N] = epilogue(A[M,K] @ Wt[N,K]^T + bias [, R])
// 128x128 block, BK=32, 128 thr = 4 warps (2x2), warp tile 64x64, m16n8k16.
enum { EPI_BIAS = 0, EPI_GELU = 1, EPI_RES = 2 };

template <int EPI, int OUTH>
__global__ void __launch_bounds__(128, 2) gemm_h(const __half* __restrict__ A,
                                                 const __half* __restrict__ Wt,
                                                 const float* __restrict__ bias,
                                                 const float* __restrict__ R,
                                                 float* __restrict__ Cf,
                                                 __half* __restrict__ Ch,
                                                 int M, int N, int K)
{
    __shared__ __align__(16) __half As[3][128][40];   // [m][k]
    __shared__ __align__(16) __half Bs[3][128][40];   // [n][k]

    const int bm = blockIdx.y * 128, bn = blockIdx.x * 128;
    const int tid = threadIdx.x;
    const int warp = tid >> 5, lane = tid & 31;
    const int wm = (warp & 1) * 64, wn = (warp >> 1) * 64;
    const int g = lane >> 2, t4 = lane & 3;

    const int srow = tid >> 2, sch = (tid & 3) * 8;

    float acc[4][8][4];
    #pragma unroll
    for (int mi = 0; mi < 4; mi++)
        #pragma unroll
        for (int ni = 0; ni < 8; ni++)
            #pragma unroll
            for (int c = 0; c < 4; c++) acc[mi][ni][c] = 0.0f;

    const int nk = K >> 5;

    // prologue: stages 0, 1
    #pragma unroll
    for (int st = 0; st < 2; st++) {
        const int k0 = st * 32;
        #pragma unroll
        for (int i = 0; i < 4; i++) {
            const int r = srow + i * 32;
            cp16(smem_u32(&As[st][r][sch]), A + (size_t)(bm + r) * K + k0 + sch);
            cp16(smem_u32(&Bs[st][r][sch]), Wt + (size_t)(bn + r) * K + k0 + sch);
        }
        cp_commit();
    }

    int s = 0;
    for (int kt = 0; kt < nk; kt++) {
        if (kt + 2 < nk) {
            const int k0 = (kt + 2) * 32;
            const int sn = (s + 2) % 3;
            #pragma unroll
            for (int i = 0; i < 4; i++) {
                const int r = srow + i * 32;
                cp16(smem_u32(&As[sn][r][sch]), A + (size_t)(bm + r) * K + k0 + sch);
                cp16(smem_u32(&Bs[sn][r][sch]), Wt + (size_t)(bn + r) * K + k0 + sch);
            }
            cp_commit();
            cp_wait<2>();
        } else if (kt + 1 < nk) {
            cp_wait<1>();
        } else {
            cp_wait<0>();
        }
        __syncthreads();

        #pragma unroll
        for (int ks = 0; ks < 2; ks++) {
            const int kc = 16 * ks + 2 * t4;
            uint32_t a[4][4];
            #pragma unroll
            for (int mi = 0; mi < 4; mi++) {
                const int rm = wm + 16 * mi;
                a[mi][0] = ld_h2(&As[s][rm + g][kc]);
                a[mi][1] = ld_h2(&As[s][rm + g + 8][kc]);
                a[mi][2] = ld_h2(&As[s][rm + g][kc + 8]);
                a[mi][3] = ld_h2(&As[s][rm + g + 8][kc + 8]);
            }
            #pragma unroll
            for (int ni = 0; ni < 8; ni++) {
                const uint32_t b0 = ld_h2(&Bs[s][wn + 8 * ni + g][kc]);
                const uint32_t b1 = ld_h2(&Bs[s][wn + 8 * ni + g][kc + 8]);
                #pragma unroll
                for (int mi = 0; mi < 4; mi++)
                    mma_f16(acc[mi][ni], a[mi][0], a[mi][1], a[mi][2], a[mi][3], b0, b1);
            }
        }
        __syncthreads();
        s = (s + 1) % 3;
    }

    // epilogue
    #pragma unroll
    for (int mi = 0; mi < 4; mi++) {
        const int r0 = bm + wm + mi * 16 + g;
        #pragma unroll
        for (int ni = 0; ni < 8; ni++) {
            const int col = bn + wn + ni * 8 + t4 * 2;
            const float b0 = bias[col], b1 = bias[col + 1];
            float v[4];
            v[0] = acc[mi][ni][0] + b0;
            v[1] = acc[mi][ni][1] + b1;
            v[2] = acc[mi][ni][2] + b0;
            v[3] = acc[mi][ni][3] + b1;
            if (EPI == EPI_GELU) {
                #pragma unroll
                for (int c = 0; c < 4; c++)
                    v[c] = 0.5f * v[c] * (1.0f + erff(v[c] * 0.70710678118654752f));
            }
            if (EPI == EPI_RES) {
                const float2 r4a = *(const float2*)(R + (size_t)r0 * N + col);
                const float2 r4b = *(const float2*)(R + (size_t)(r0 + 8) * N + col);
                v[0] += r4a.x; v[1] += r4a.y;
                v[2] += r4b.x; v[3] += r4b.y;
            }
            if (OUTH) {
                *(__half2*)(Ch + (size_t)r0 * N + col)       = __floats2half2_rn(v[0], v[1]);
                *(__half2*)(Ch + (size_t)(r0 + 8) * N + col) = __floats2half2_rn(v[2], v[3]);
            } else {
                *(float2*)(Cf + (size_t)r0 * N + col)       = make_float2(v[0], v[1]);
                *(float2*)(Cf + (size_t)(r0 + 8) * N + col) = make_float2(v[2], v[3]);
            }
        }
    }
}

// ---------------- Flash attention: in-register P, 3-stage K/V ----------------
// Block: 128 queries x one (b,h); 8 warps x 16 q-rows; 64-key tiles.
// S C-fragments are re-packed in registers as PV A-fragments (no smem P).
#define NIT (SEQ / 64)

__global__ void __launch_bounds__(256, 2) attn_h_kernel(const float* __restrict__ table,
                                                        __half* __restrict__ out)
{
    __shared__ __align__(16) __half Ks[3][64][40];   // [key][d]
    __shared__ __align__(16) __half Vt[3][32][72];   // [d][key]
    __shared__ float tbl[TBLN];                      // per-head bias table column

    const int b = blockIdx.z, h = blockIdx.y, q0 = blockIdx.x * 128;
    const int tid = threadIdx.x;
    const int warp = tid >> 5, lane = tid & 31;
    const int g = lane >> 2, t4 = lane & 3;
    const int wq = warp * 16;

    const float scale = 0.17677669529663687f;  // 1/sqrt(32)

    // staging maps
    const int kkey = tid >> 2, kch = (tid & 3) * 8;   // K: 64 keys x 4 chunks
    const int vd = tid >> 3, vch = (tid & 7) * 8;     // Vt: 32 d x 8 chunks

    const __half* kbase = g_qkv + (size_t)(b * SEQ + kkey) * (3 * DIM)
                          + DIM + h * HD + kch;
    const __half* vbase = g_vt + ((size_t)(b * HEADS + h) * HD + vd) * SEQ + vch;

    // prologue: stages 0, 1
    #pragma unroll
    for (int st = 0; st < 2; st++) {
        cp16(smem_u32(&Ks[st][kkey][kch]), kbase + (size_t)(st * 64) * (3 * DIM));
        cp16(smem_u32(&Vt[st][vd][vch]), vbase + st * 64);
        cp_commit();
    }

    // per-head bias table column -> smem (regular loads; not in cp groups)
    for (int i = tid; i < TBLN; i += 256) tbl[i] = table[i * HEADS + h];

    // Q fragments (raw fp16; scale folded into post-mma FFMA)
    uint32_t qf[2][4];
    {
        const __half* q0p = g_qkv + (size_t)(b * SEQ + q0 + wq + g) * (3 * DIM) + h * HD;
        const __half* q1p = q0p + 8 * (3 * DIM);
        #pragma unroll
        for (int ks = 0; ks < 2; ks++) {
            const int kc = 16 * ks + 2 * t4;
            qf[ks][0] = ld_h2(q0p + kc);
            qf[ks][1] = ld_h2(q1p + kc);
            qf[ks][2] = ld_h2(q0p + kc + 8);
            qf[ks][3] = ld_h2(q1p + kc + 8);
        }
    }

    // rel-index bases: ri = (ly - my)*63 + (lx - mx) + 1984
    const int l0 = q0 + wq + g, l1 = l0 + 8;
    const int Cb0 = (l0 >> 5) * 63 + (l0 & 31) + 1984;
    const int Cb1 = (l1 >> 5) * 63 + (l1 & 31) + 1984;

    float m0 = -1e30f, m1 = -1e30f, li0 = 0.0f, li1 = 0.0f;
    float acc_o[4][4];
    #pragma unroll
    for (int ni = 0; ni < 4; ni++)
        #pragma unroll
        for (int c = 0; c < 4; c++) acc_o[ni][c] = 0.0f;

    for (int it = 0; it < NIT; it++) {
        const int s = it % 3;
        if (it + 1 < NIT) cp_wait<1>(); else cp_wait<0>();
        __syncthreads();
        if (it + 2 < NIT) {
            const int sn = (it + 2) % 3;
            cp16(smem_u32(&Ks[sn][kkey][kch]),
                 kbase + (size_t)((it + 2) * 64) * (3 * DIM));
            cp16(smem_u32(&Vt[sn][vd][vch]), vbase + (it + 2) * 64);
            cp_commit();
        }

        // ---- S = Q @ K^T ----
        float sacc[8][4];
        #pragma unroll
        for (int ni = 0; ni < 8; ni++)
            #pragma unroll
            for (int c = 0; c < 4; c++) sacc[ni][c] = 0.0f;
        #pragma unroll
        for (int ks = 0; ks < 2; ks++) {
            const int kc = 16 * ks + 2 * t4;
            #pragma unroll
            for (int ni = 0; ni < 8; ni++) {
                const uint32_t b0 = ld_h2(&Ks[s][ni * 8 + g][kc]);
                const uint32_t b1 = ld_h2(&Ks[s][ni * 8 + g][kc + 8]);
                mma_f16(sacc[ni], qf[ks][0], qf[ks][1], qf[ks][2], qf[ks][3], b0, b1);
            }
        }
        // ---- scale + rel-pos bias from smem table ----
        const int k0 = it * 64;
        {
            const int base0 = Cb0 - (k0 >> 5) * 63;
            const int base1 = Cb1 - (k0 >> 5) * 63;
            #pragma unroll
            for (int ni = 0; ni < 8; ni++) {
                const int off = (ni >> 2) * 63 + 8 * (ni & 3) + 2 * t4;
                sacc[ni][0] = fmaf(sacc[ni][0], scale, tbl[base0 - off]);
                sacc[ni][1] = fmaf(sacc[ni][1], scale, tbl[base0 - off - 1]);
                sacc[ni][2] = fmaf(sacc[ni][2], scale, tbl[base1 - off]);
                sacc[ni][3] = fmaf(sacc[ni][3], scale, tbl[base1 - off - 1]);
            }
        }

        // ---- online softmax (registers only) ----
        float vmax0 = -1e30f, vmax1 = -1e30f;
        #pragma unroll
        for (int ni = 0; ni < 8; ni++) {
            vmax0 = fmaxf(vmax0, fmaxf(sacc[ni][0], sacc[ni][1]));
            vmax1 = fmaxf(vmax1, fmaxf(sacc[ni][2], sacc[ni][3]));
        }
        #pragma unroll
        for (int o = 1; o <= 2; o <<= 1) {
            vmax0 = fmaxf(vmax0, __shfl_xor_sync(0xffffffffu, vmax0, o));
            vmax1 = fmaxf(vmax1, __shfl_xor_sync(0xffffffffu, vmax1, o));
        }
        const float nm0 = fmaxf(m0, vmax0);
        const float nm1 = fmaxf(m1, vmax1);
        const float corr0 = __expf(m0 - nm0);
        const float corr1 = __expf(m1 - nm1);
        m0 = nm0; m1 = nm1;
        float rs0 = 0.0f, rs1 = 0.0f;

        // exp -> packed fp16 PV A-fragments (C-layout == A-layout, same lane)
        uint32_t ph2[8][2];
        #pragma unroll
        for (int ni = 0; ni < 8; ni++) {
            const float p0 = __expf(sacc[ni][0] - m0);
            const float p1 = __expf(sacc[ni][1] - m0);
            const float p2 = __expf(sacc[ni][2] - m1);
            const float p3 = __expf(sacc[ni][3] - m1);
            rs0 += p0 + p1; rs1 += p2 + p3;
            ph2[ni][0] = pack_h2(p0, p1);   // rows g,   cols ni*8+2t4..+1
            ph2[ni][1] = pack_h2(p2, p3);   // rows g+8, same cols
        }
        li0 = li0 * corr0 + rs0;
        li1 = li1 * corr1 + rs1;
        #pragma unroll
        for (int ni = 0; ni < 4; ni++) {
            acc_o[ni][0] *= corr0; acc_o[ni][1] *= corr0;
            acc_o[ni][2] *= corr1; acc_o[ni][3] *= corr1;
        }

        // ---- O += P @ V  (A-frags straight from ph2) ----
        #pragma unroll
        for (int ks = 0; ks < 4; ks++) {
            const int kc = 16 * ks + 2 * t4;
            const uint32_t a0 = ph2[2 * ks][0];
            const uint32_t a1 = ph2[2 * ks][1];
            const uint32_t a2 = ph2[2 * ks + 1][0];
            const uint32_t a3 = ph2[2 * ks + 1][1];
            #pragma unroll
            for (int ni = 0; ni < 4; ni++) {
                const uint32_t b0 = ld_h2(&Vt[s][ni * 8 + g][kc]);
                const uint32_t b1 = ld_h2(&Vt[s][ni * 8 + g][kc + 8]);
                mma_f16(acc_o[ni], a0, a1, a2, a3, b0, b1);
            }
        }
    }

    // ---- finalize ----
    #pragma unroll
    for (int o = 1; o <= 2; o <<= 1) {
        li0 += __shfl_xor_sync(0xffffffffu, li0, o);
        li1 += __shfl_xor_sync(0xffffffffu, li1, o);
    }
    const float inv0 = 1.0f / li0;
    const float inv1 = 1.0f / li1;
    __half* o0p = out + (size_t)(b * SEQ + q0 + wq + g) * DIM + h * HD;
    __half* o1p = o0p + 8 * DIM;
    #pragma unroll
    for (int ni = 0; ni < 4; ni++) {
        const int col = ni * 8 + t4 * 2;
        *(__half2*)(o0p + col) = __floats2half2_rn(acc_o[ni][0] * inv0,
                                                   acc_o[ni][1] * inv0);
        *(__half2*)(o1p + col) = __floats2half2_rn(acc_o[ni][2] * inv1,
                                                   acc_o[ni][3] * inv1);
    }
}

// ---------------- launch -----------------------------------------------------
extern "C" void kernel_launch(void* const* d_in, const int* in_sizes, int n_in,
                              void* d_out, int out_size)
{
    const float* x      = (const float*)d_in[0];
    const float* table  = (const float*)d_in[2];
    const float* qkv_w  = (const float*)d_in[3];
    const float* qkv_b  = (const float*)d_in[4];
    const float* proj_w = (const float*)d_in[5];
    const float* proj_b = (const float*)d_in[6];
    const float* n1_g   = (const float*)d_in[7];
    const float* n1_b   = (const float*)d_in[8];
    const float* n2_g   = (const float*)d_in[9];
    const float* n2_b   = (const float*)d_in[10];
    const float* fc1_w  = (const float*)d_in[11];
    const float* fc1_b  = (const float*)d_in[12];
    const float* fc2_w  = (const float*)d_in[13];
    const float* fc2_b  = (const float*)d_in[14];
    float* out = (float*)d_out;

    __half *h, *qkv, *attnout, *mlp1, *w;
    float *xres;
    cudaGetSymbolAddress((void**)&h,       g_h);
    cudaGetSymbolAddress((void**)&qkv,     g_qkv);
    cudaGetSymbolAddress((void**)&attnout, g_attnout);
    cudaGetSymbolAddress((void**)&xres,    g_xres);
    cudaGetSymbolAddress((void**)&mlp1,    g_mlp1);
    cudaGetSymbolAddress((void**)&w,       g_w);

    dim3 tb(32, 8);
    // 0. transpose + convert weights -> fp16 [N][K]
    cvt_t_kernel<<<dim3(48, 16), tb>>>(qkv_w,  w + W_QKV,  DIM,  3 * DIM);
    cvt_t_kernel<<<dim3(16, 16), tb>>>(proj_w, w + W_PROJ, DIM,  DIM);
    cvt_t_kernel<<<dim3(64, 16), tb>>>(fc1_w,  w + W_FC1,  DIM,  MLPH);
    cvt_t_kernel<<<dim3(16, 64), tb>>>(fc2_w,  w + W_FC2,  MLPH, DIM);
    // 1. h = LN1(x)
    ln_kernel<<<MROWS, 128>>>(x, n1_g, n1_b, h);
    // 2. qkv = fp16(h @ qkv_w + qkv_b)
    gemm_h<EPI_BIAS, 1><<<dim3(12, 64), 128>>>(h, w + W_QKV, qkv_b, nullptr,
                                               nullptr, qkv, MROWS, 3 * DIM, DIM);
    // 3. V transpose
    vt_kernel<<<dim3(SEQ / 32, HEADS, BATCH), tb>>>();
    // 4. flash attention (in-register P) -> fp16 [B, L, C]
    attn_h_kernel<<<dim3(8, HEADS, BATCH), 256>>>(table, attnout);
    // 5. xres = x + attnout @ proj_w + proj_b  (fp32)
    gemm_h<EPI_RES, 0><<<dim3(4, 64), 128>>>(attnout, w + W_PROJ, proj_b, x,
                                             xres, nullptr, MROWS, DIM, DIM);
    // 6. h = LN2(xres)
    ln_kernel<<<MROWS, 128>>>(xres, n2_g, n2_b, h);
    // 7. mlp1 = fp16(gelu(h @ fc1_w + fc1_b))
    gemm_h<EPI_GELU, 1><<<dim3(16, 64), 128>>>(h, w + W_FC1, fc1_b, nullptr,
                                               nullptr, mlp1, MROWS, MLPH, DIM);
    // 8. out = xres + mlp1 @ fc2_w + fc2_b  (fp32)
    gemm_h<EPI_RES, 0><<<dim3(4, 64), 128>>>(mlp1, w + W_FC2, fc2_b, xres,
                                             out, nullptr, MROWS, DIM, MLPH);
}

// round 13
// speedup vs baseline: 2.0090x; 1.0430x over previous
#include <cuda_runtime.h>
#include <cuda_fp16.h>
#include <math.h>
#include <stdint.h>

#define BATCH 8
#define SEQ 1024
#define DIM 512
#define HEADS 16
#define HD 32
#define MROWS (BATCH*SEQ)   /* 8192 */
#define MLPH 2048
#define TBLN 3969           /* (2*32-1)^2 */

// ---------------- scratch (device globals; no allocations allowed) ----------
__device__ __align__(256) __half g_h[MROWS * DIM];         // LN out (fp16)
__device__ __align__(256) __half g_qkv[MROWS * 3 * DIM];   // q|k|v (fp16)
__device__ __align__(256) __half g_vt[BATCH * HEADS * HD * SEQ]; // V^T per (b,h)
__device__ __align__(256) __half g_attnout[MROWS * DIM];   // attention out (fp16)
__device__ __align__(256) __half g_mlp1[MROWS * MLPH];     // gelu(fc1) (fp16)
__device__ __align__(256) __half g_w[3145728];             // [N][K] fp16 weights
__device__ float g_xres[MROWS * DIM];                      // x + proj(attn) fp32
__device__ float g_tblt[HEADS * TBLN];                     // transposed bias table

#define W_QKV  0
#define W_PROJ 786432
#define W_FC1  1048576
#define W_FC2  2097152

// ---------------- helpers ----------------------------------------------------
__device__ __forceinline__ void mma_f16(float* c, uint32_t a0, uint32_t a1,
                                        uint32_t a2, uint32_t a3,
                                        uint32_t b0, uint32_t b1) {
    asm volatile(
        "mma.sync.aligned.m16n8k16.row.col.f32.f16.f16.f32 "
        "{%0,%1,%2,%3}, {%4,%5,%6,%7}, {%8,%9}, {%0,%1,%2,%3};"
        : "+f"(c[0]), "+f"(c[1]), "+f"(c[2]), "+f"(c[3])
        : "r"(a0), "r"(a1), "r"(a2), "r"(a3), "r"(b0), "r"(b1));
}

__device__ __forceinline__ void cp16(uint32_t s, const void* g) {
    asm volatile("cp.async.cg.shared.global [%0], [%1], 16;\n" :: "r"(s), "l"(g));
}
__device__ __forceinline__ void cp_commit() {
    asm volatile("cp.async.commit_group;\n");
}
template <int N> __device__ __forceinline__ void cp_wait() {
    asm volatile("cp.async.wait_group %0;\n" :: "n"(N));
}
__device__ __forceinline__ uint32_t smem_u32(const void* p) {
    uint32_t a;
    asm("{ .reg .u64 t; cvta.to.shared.u64 t, %1; cvt.u32.u64 %0, t; }"
        : "=r"(a) : "l"(p));
    return a;
}
__device__ __forceinline__ uint32_t ld_h2(const __half* p) {
    return *(const uint32_t*)p;
}
__device__ __forceinline__ uint32_t pack_h2(float lo, float hi) {
    const __half2 h = __floats2half2_rn(lo, hi);
    return *(const uint32_t*)&h;
}

// ---------------- merged weight transpose + fp16 convert ---------------------
// One launch for all 4 weights. in: [K][N] fp32.  out: [N][K] fp16.
__global__ void __launch_bounds__(256) cvt_all_kernel(const float* __restrict__ qkv_w,
                                                      const float* __restrict__ proj_w,
                                                      const float* __restrict__ fc1_w,
                                                      const float* __restrict__ fc2_w,
                                                      __half* __restrict__ w)
{
    __shared__ float tile[32][33];
    const int bid = blockIdx.x;
    const float* in;
    __half* out;
    int K, N, tid2;
    if (bid < 768)       { in = qkv_w;  out = w + W_QKV;  K = DIM;  N = 3 * DIM; tid2 = bid; }
    else if (bid < 1024) { in = proj_w; out = w + W_PROJ; K = DIM;  N = DIM;     tid2 = bid - 768; }
    else if (bid < 2048) { in = fc1_w;  out = w + W_FC1;  K = DIM;  N = MLPH;    tid2 = bid - 1024; }
    else                 { in = fc2_w;  out = w + W_FC2;  K = MLPH; N = DIM;     tid2 = bid - 2048; }
    const int ntx = N >> 5;
    const int bn = (tid2 % ntx) * 32, bk = (tid2 / ntx) * 32;
    const int tx = threadIdx.x, ty = threadIdx.y;
    #pragma unroll
    for (int i = 0; i < 4; i++)
        tile[ty + 8 * i][tx] = in[(size_t)(bk + ty + 8 * i) * N + bn + tx];
    __syncthreads();
    #pragma unroll
    for (int i = 0; i < 4; i++) {
        const int n = ty + 8 * i;
        out[(size_t)(bn + n) * K + bk + tx] = __float2half_rn(tile[tx][n]);
    }
}

// ---------------- bias-table transpose: g_tblt[h][i] = table[i*16+h] ---------
__global__ void __launch_bounds__(256) tblt_kernel(const float* __restrict__ table)
{
    const int i = blockIdx.x * 256 + threadIdx.x;
    if (i < TBLN) {
        #pragma unroll
        for (int h = 0; h < HEADS; h++)
            g_tblt[h * TBLN + i] = table[i * HEADS + h];
    }
}

// ---------------- V transpose: g_qkv v-section -> Vt[b][h][d][seq] -----------
__global__ void __launch_bounds__(256) vt_kernel()
{
    __shared__ __half tile[32][34];
    const int m0 = blockIdx.x * 32, h = blockIdx.y, b = blockIdx.z;
    const int tx = threadIdx.x, ty = threadIdx.y;
    const __half* in = g_qkv + (size_t)(b * SEQ) * (3 * DIM) + 2 * DIM + h * HD;
    #pragma unroll
    for (int i = 0; i < 4; i++)
        tile[ty + 8 * i][tx] = in[(size_t)(m0 + ty + 8 * i) * (3 * DIM) + tx];
    __syncthreads();
    __half* out = g_vt + ((size_t)(b * HEADS + h) * HD) * SEQ + m0;
    #pragma unroll
    for (int i = 0; i < 4; i++) {
        const int d = ty + 8 * i;
        out[(size_t)d * SEQ + tx] = tile[tx][d];
    }
}

// ---------------- LayerNorm (fp16 output) ------------------------------------
__global__ void __launch_bounds__(128) ln_kernel(const float* __restrict__ x,
                                                 const float* __restrict__ g,
                                                 const float* __restrict__ b,
                                                 __half* __restrict__ out)
{
    const int row = blockIdx.x;
    const int t = threadIdx.x;
    const float4 v = ((const float4*)(x + (size_t)row * DIM))[t];
    float s  = v.x + v.y + v.z + v.w;
    float s2 = v.x*v.x + v.y*v.y + v.z*v.z + v.w*v.w;
    #pragma unroll
    for (int o = 16; o > 0; o >>= 1) {
        s  += __shfl_xor_sync(0xffffffffu, s,  o);
        s2 += __shfl_xor_sync(0xffffffffu, s2, o);
    }
    __shared__ float rs[4], rs2[4];
    if ((t & 31) == 0) { rs[t >> 5] = s; rs2[t >> 5] = s2; }
    __syncthreads();
    s  = rs[0] + rs[1] + rs[2] + rs[3];
    s2 = rs2[0] + rs2[1] + rs2[2] + rs2[3];
    const float mean = s * (1.0f / DIM);
    const float var  = s2 * (1.0f / DIM) - mean * mean;
    const float inv  = rsqrtf(var + 1e-5f);
    const float4 gg = ((const float4*)g)[t];
    const float4 bb = ((const float4*)b)[t];
    __half2* op = (__half2*)(out + (size_t)row * DIM + 4 * t);
    op[0] = __floats2half2_rn((v.x - mean) * inv * gg.x + bb.x,
                              (v.y - mean) * inv * gg.y + bb.y);
    op[1] = __floats2half2_rn((v.z - mean) * inv * gg.z + bb.z,
                              (v.w - mean) * inv * gg.w + bb.w);
}

// ---------------- fp16 tensor-core GEMM, 3-stage cp.async pipeline -----------
// C[M,N] = epilogue(A[M,K] @ Wt[N,K]^T + bias [, R])
// 128x128 block, BK=32, 128 thr = 4 warps (2x2), warp tile 64x64, m16n8k16.
enum { EPI_BIAS = 0, EPI_GELU = 1, EPI_RES = 2 };

template <int EPI, int OUTH>
__global__ void __launch_bounds__(128, 2) gemm_h(const __half* __restrict__ A,
                                                 const __half* __restrict__ Wt,
                                                 const float* __restrict__ bias,
                                                 const float* __restrict__ R,
                                                 float* __restrict__ Cf,
                                                 __half* __restrict__ Ch,
                                                 int M, int N, int K)
{
    __shared__ __align__(16) __half As[3][128][40];   // [m][k]
    __shared__ __align__(16) __half Bs[3][128][40];   // [n][k]

    const int bm = blockIdx.y * 128, bn = blockIdx.x * 128;
    const int tid = threadIdx.x;
    const int warp = tid >> 5, lane = tid & 31;
    const int wm = (warp & 1) * 64, wn = (warp >> 1) * 64;
    const int g = lane >> 2, t4 = lane & 3;

    const int srow = tid >> 2, sch = (tid & 3) * 8;

    float acc[4][8][4];
    #pragma unroll
    for (int mi = 0; mi < 4; mi++)
        #pragma unroll
        for (int ni = 0; ni < 8; ni++)
            #pragma unroll
            for (int c = 0; c < 4; c++) acc[mi][ni][c] = 0.0f;

    const int nk = K >> 5;

    #pragma unroll
    for (int st = 0; st < 2; st++) {
        const int k0 = st * 32;
        #pragma unroll
        for (int i = 0; i < 4; i++) {
            const int r = srow + i * 32;
            cp16(smem_u32(&As[st][r][sch]), A + (size_t)(bm + r) * K + k0 + sch);
            cp16(smem_u32(&Bs[st][r][sch]), Wt + (size_t)(bn + r) * K + k0 + sch);
        }
        cp_commit();
    }

    int s = 0;
    for (int kt = 0; kt < nk; kt++) {
        if (kt + 2 < nk) {
            const int k0 = (kt + 2) * 32;
            const int sn = (s + 2) % 3;
            #pragma unroll
            for (int i = 0; i < 4; i++) {
                const int r = srow + i * 32;
                cp16(smem_u32(&As[sn][r][sch]), A + (size_t)(bm + r) * K + k0 + sch);
                cp16(smem_u32(&Bs[sn][r][sch]), Wt + (size_t)(bn + r) * K + k0 + sch);
            }
            cp_commit();
            cp_wait<2>();
        } else if (kt + 1 < nk) {
            cp_wait<1>();
        } else {
            cp_wait<0>();
        }
        __syncthreads();

        #pragma unroll
        for (int ks = 0; ks < 2; ks++) {
            const int kc = 16 * ks + 2 * t4;
            uint32_t a[4][4];
            #pragma unroll
            for (int mi = 0; mi < 4; mi++) {
                const int rm = wm + 16 * mi;
                a[mi][0] = ld_h2(&As[s][rm + g][kc]);
                a[mi][1] = ld_h2(&As[s][rm + g + 8][kc]);
                a[mi][2] = ld_h2(&As[s][rm + g][kc + 8]);
                a[mi][3] = ld_h2(&As[s][rm + g + 8][kc + 8]);
            }
            #pragma unroll
            for (int ni = 0; ni < 8; ni++) {
                const uint32_t b0 = ld_h2(&Bs[s][wn + 8 * ni + g][kc]);
                const uint32_t b1 = ld_h2(&Bs[s][wn + 8 * ni + g][kc + 8]);
                #pragma unroll
                for (int mi = 0; mi < 4; mi++)
                    mma_f16(acc[mi][ni], a[mi][0], a[mi][1], a[mi][2], a[mi][3], b0, b1);
            }
        }
        __syncthreads();
        s = (s + 1) % 3;
    }

    #pragma unroll
    for (int mi = 0; mi < 4; mi++) {
        const int r0 = bm + wm + mi * 16 + g;
        #pragma unroll
        for (int ni = 0; ni < 8; ni++) {
            const int col = bn + wn + ni * 8 + t4 * 2;
            const float b0 = bias[col], b1 = bias[col + 1];
            float v[4];
            v[0] = acc[mi][ni][0] + b0;
            v[1] = acc[mi][ni][1] + b1;
            v[2] = acc[mi][ni][2] + b0;
            v[3] = acc[mi][ni][3] + b1;
            if (EPI == EPI_GELU) {
                #pragma unroll
                for (int c = 0; c < 4; c++)
                    v[c] = 0.5f * v[c] * (1.0f + erff(v[c] * 0.70710678118654752f));
            }
            if (EPI == EPI_RES) {
                const float2 r4a = *(const float2*)(R + (size_t)r0 * N + col);
                const float2 r4b = *(const float2*)(R + (size_t)(r0 + 8) * N + col);
                v[0] += r4a.x; v[1] += r4a.y;
                v[2] += r4b.x; v[3] += r4b.y;
            }
            if (OUTH) {
                *(__half2*)(Ch + (size_t)r0 * N + col)       = __floats2half2_rn(v[0], v[1]);
                *(__half2*)(Ch + (size_t)(r0 + 8) * N + col) = __floats2half2_rn(v[2], v[3]);
            } else {
                *(float2*)(Cf + (size_t)r0 * N + col)       = make_float2(v[0], v[1]);
                *(float2*)(Cf + (size_t)(r0 + 8) * N + col) = make_float2(v[2], v[3]);
            }
        }
    }
}

// ---------------- Flash attention: 64-query blocks, 4 blocks/SM --------------
// Block: 64 queries x one (b,h); 4 warps x 16 q-rows; 64-key tiles, 3-stage.
// In-register P (S C-frags re-packed as PV A-frags).
#define NIT (SEQ / 64)

__global__ void __launch_bounds__(128, 4) attn_h_kernel(__half* __restrict__ out)
{
    __shared__ __align__(16) __half Ks[3][64][40];   // [key][d]
    __shared__ __align__(16) __half Vt[3][32][72];   // [d][key]
    __shared__ float tbl[TBLN];                      // per-head bias table column

    const int b = blockIdx.z, h = blockIdx.y, q0 = blockIdx.x * 64;
    const int tid = threadIdx.x;
    const int warp = tid >> 5, lane = tid & 31;
    const int g = lane >> 2, t4 = lane & 3;
    const int wq = warp * 16;

    const float scale = 0.17677669529663687f;  // 1/sqrt(32)

    // staging maps (128 threads)
    const int kkey = tid >> 2, kch = (tid & 3) * 8;   // K: keys kkey, kkey+32
    const int vd = tid >> 3, vch = (tid & 7) * 8;     // Vt: d rows vd, vd+16

    const __half* kbase = g_qkv + (size_t)(b * SEQ + kkey) * (3 * DIM)
                          + DIM + h * HD + kch;
    const __half* vbase = g_vt + ((size_t)(b * HEADS + h) * HD + vd) * SEQ + vch;
    const size_t kstep = (size_t)32 * (3 * DIM);
    const size_t vstep = (size_t)16 * SEQ;

    // prologue: stages 0, 1
    #pragma unroll
    for (int st = 0; st < 2; st++) {
        cp16(smem_u32(&Ks[st][kkey][kch]), kbase + (size_t)(st * 64) * (3 * DIM));
        cp16(smem_u32(&Ks[st][kkey + 32][kch]),
             kbase + (size_t)(st * 64) * (3 * DIM) + kstep);
        cp16(smem_u32(&Vt[st][vd][vch]), vbase + st * 64);
        cp16(smem_u32(&Vt[st][vd + 16][vch]), vbase + st * 64 + vstep);
        cp_commit();
    }

    // per-head bias table column -> smem (contiguous from transposed table)
    {
        const float* tsrc = g_tblt + (size_t)h * TBLN;
        for (int i = tid; i < TBLN; i += 128) tbl[i] = tsrc[i];
    }

    // Q fragments (raw fp16; scale folded into post-mma FFMA)
    uint32_t qf[2][4];
    {
        const __half* q0p = g_qkv + (size_t)(b * SEQ + q0 + wq + g) * (3 * DIM) + h * HD;
        const __half* q1p = q0p + 8 * (3 * DIM);
        #pragma unroll
        for (int ks = 0; ks < 2; ks++) {
            const int kc = 16 * ks + 2 * t4;
            qf[ks][0] = ld_h2(q0p + kc);
            qf[ks][1] = ld_h2(q1p + kc);
            qf[ks][2] = ld_h2(q0p + kc + 8);
            qf[ks][3] = ld_h2(q1p + kc + 8);
        }
    }

    // rel-index bases: ri = (ly - my)*63 + (lx - mx) + 1984
    const int l0 = q0 + wq + g, l1 = l0 + 8;
    const int Cb0 = (l0 >> 5) * 63 + (l0 & 31) + 1984;
    const int Cb1 = (l1 >> 5) * 63 + (l1 & 31) + 1984;

    float m0 = -1e30f, m1 = -1e30f, li0 = 0.0f, li1 = 0.0f;
    float acc_o[4][4];
    #pragma unroll
    for (int ni = 0; ni < 4; ni++)
        #pragma unroll
        for (int c = 0; c < 4; c++) acc_o[ni][c] = 0.0f;

    for (int it = 0; it < NIT; it++) {
        const int s = it % 3;
        if (it + 1 < NIT) cp_wait<1>(); else cp_wait<0>();
        __syncthreads();
        if (it + 2 < NIT) {
            const int sn = (it + 2) % 3;
            const size_t ko = (size_t)((it + 2) * 64) * (3 * DIM);
            cp16(smem_u32(&Ks[sn][kkey][kch]), kbase + ko);
            cp16(smem_u32(&Ks[sn][kkey + 32][kch]), kbase + ko + kstep);
            cp16(smem_u32(&Vt[sn][vd][vch]), vbase + (it + 2) * 64);
            cp16(smem_u32(&Vt[sn][vd + 16][vch]), vbase + (it + 2) * 64 + vstep);
            cp_commit();
        }

        // ---- S = Q @ K^T ----
        float sacc[8][4];
        #pragma unroll
        for (int ni = 0; ni < 8; ni++)
            #pragma unroll
            for (int c = 0; c < 4; c++) sacc[ni][c] = 0.0f;
        #pragma unroll
        for (int ks = 0; ks < 2; ks++) {
            const int kc = 16 * ks + 2 * t4;
            #pragma unroll
            for (int ni = 0; ni < 8; ni++) {
                const uint32_t b0 = ld_h2(&Ks[s][ni * 8 + g][kc]);
                const uint32_t b1 = ld_h2(&Ks[s][ni * 8 + g][kc + 8]);
                mma_f16(sacc[ni], qf[ks][0], qf[ks][1], qf[ks][2], qf[ks][3], b0, b1);
            }
        }
        // ---- scale + rel-pos bias from smem table ----
        const int k0 = it * 64;
        {
            const int base0 = Cb0 - (k0 >> 5) * 63;
            const int base1 = Cb1 - (k0 >> 5) * 63;
            #pragma unroll
            for (int ni = 0; ni < 8; ni++) {
                const int off = (ni >> 2) * 63 + 8 * (ni & 3) + 2 * t4;
                sacc[ni][0] = fmaf(sacc[ni][0], scale, tbl[base0 - off]);
                sacc[ni][1] = fmaf(sacc[ni][1], scale, tbl[base0 - off - 1]);
                sacc[ni][2] = fmaf(sacc[ni][2], scale, tbl[base1 - off]);
                sacc[ni][3] = fmaf(sacc[ni][3], scale, tbl[base1 - off - 1]);
            }
        }

        // ---- online softmax (registers only) ----
        float vmax0 = -1e30f, vmax1 = -1e30f;
        #pragma unroll
        for (int ni = 0; ni < 8; ni++) {
            vmax0 = fmaxf(vmax0, fmaxf(sacc[ni][0], sacc[ni][1]));
            vmax1 = fmaxf(vmax1, fmaxf(sacc[ni][2], sacc[ni][3]));
        }
        #pragma unroll
        for (int o = 1; o <= 2; o <<= 1) {
            vmax0 = fmaxf(vmax0, __shfl_xor_sync(0xffffffffu, vmax0, o));
            vmax1 = fmaxf(vmax1, __shfl_xor_sync(0xffffffffu, vmax1, o));
        }
        const float nm0 = fmaxf(m0, vmax0);
        const float nm1 = fmaxf(m1, vmax1);
        const float corr0 = __expf(m0 - nm0);
        const float corr1 = __expf(m1 - nm1);
        m0 = nm0; m1 = nm1;
        float rs0 = 0.0f, rs1 = 0.0f;

        // exp -> packed fp16 PV A-fragments (C-layout == A-layout, same lane)
        uint32_t ph2[8][2];
        #pragma unroll
        for (int ni = 0; ni < 8; ni++) {
            const float p0 = __expf(sacc[ni][0] - m0);
            const float p1 = __expf(sacc[ni][1] - m0);
            const float p2 = __expf(sacc[ni][2] - m1);
            const float p3 = __expf(sacc[ni][3] - m1);
            rs0 += p0 + p1; rs1 += p2 + p3;
            ph2[ni][0] = pack_h2(p0, p1);
            ph2[ni][1] = pack_h2(p2, p3);
        }
        li0 = li0 * corr0 + rs0;
        li1 = li1 * corr1 + rs1;
        #pragma unroll
        for (int ni = 0; ni < 4; ni++) {
            acc_o[ni][0] *= corr0; acc_o[ni][1] *= corr0;
            acc_o[ni][2] *= corr1; acc_o[ni][3] *= corr1;
        }

        // ---- O += P @ V ----
        #pragma unroll
        for (int ks = 0; ks < 4; ks++) {
            const int kc = 16 * ks + 2 * t4;
            const uint32_t a0 = ph2[2 * ks][0];
            const uint32_t a1 = ph2[2 * ks][1];
            const uint32_t a2 = ph2[2 * ks + 1][0];
            const uint32_t a3 = ph2[2 * ks + 1][1];
            #pragma unroll
            for (int ni = 0; ni < 4; ni++) {
                const uint32_t b0 = ld_h2(&Vt[s][ni * 8 + g][kc]);
                const uint32_t b1 = ld_h2(&Vt[s][ni * 8 + g][kc + 8]);
                mma_f16(acc_o[ni], a0, a1, a2, a3, b0, b1);
            }
        }
    }

    // ---- finalize ----
    #pragma unroll
    for (int o = 1; o <= 2; o <<= 1) {
        li0 += __shfl_xor_sync(0xffffffffu, li0, o);
        li1 += __shfl_xor_sync(0xffffffffu, li1, o);
    }
    const float inv0 = 1.0f / li0;
    const float inv1 = 1.0f / li1;
    __half* o0p = out + (size_t)(b * SEQ + q0 + wq + g) * DIM + h * HD;
    __half* o1p = o0p + 8 * DIM;
    #pragma unroll
    for (int ni = 0; ni < 4; ni++) {
        const int col = ni * 8 + t4 * 2;
        *(__half2*)(o0p + col) = __floats2half2_rn(acc_o[ni][0] * inv0,
                                                   acc_o[ni][1] * inv0);
        *(__half2*)(o1p + col) = __floats2half2_rn(acc_o[ni][2] * inv1,
                                                   acc_o[ni][3] * inv1);
    }
}

// ---------------- launch -----------------------------------------------------
extern "C" void kernel_launch(void* const* d_in, const int* in_sizes, int n_in,
                              void* d_out, int out_size)
{
    const float* x      = (const float*)d_in[0];
    const float* table  = (const float*)d_in[2];
    const float* qkv_w  = (const float*)d_in[3];
    const float* qkv_b  = (const float*)d_in[4];
    const float* proj_w = (const float*)d_in[5];
    const float* proj_b = (const float*)d_in[6];
    const float* n1_g   = (const float*)d_in[7];
    const float* n1_b   = (const float*)d_in[8];
    const float* n2_g   = (const float*)d_in[9];
    const float* n2_b   = (const float*)d_in[10];
    const float* fc1_w  = (const float*)d_in[11];
    const float* fc1_b  = (const float*)d_in[12];
    const float* fc2_w  = (const float*)d_in[13];
    const float* fc2_b  = (const float*)d_in[14];
    float* out = (float*)d_out;

    __half *h, *qkv, *attnout, *mlp1, *w;
    float *xres;
    cudaGetSymbolAddress((void**)&h,       g_h);
    cudaGetSymbolAddress((void**)&qkv,     g_qkv);
    cudaGetSymbolAddress((void**)&attnout, g_attnout);
    cudaGetSymbolAddress((void**)&xres,    g_xres);
    cudaGetSymbolAddress((void**)&mlp1,    g_mlp1);
    cudaGetSymbolAddress((void**)&w,       g_w);

    dim3 tb(32, 8);
    // 0. all weight transposes in one launch + bias table transpose
    cvt_all_kernel<<<3072, tb>>>(qkv_w, proj_w, fc1_w, fc2_w, w);
    tblt_kernel<<<(TBLN + 255) / 256, 256>>>(table);
    // 1. h = LN1(x)
    ln_kernel<<<MROWS, 128>>>(x, n1_g, n1_b, h);
    // 2. qkv = fp16(h @ qkv_w + qkv_b)
    gemm_h<EPI_BIAS, 1><<<dim3(12, 64), 128>>>(h, w + W_QKV, qkv_b, nullptr,
                                               nullptr, qkv, MROWS, 3 * DIM, DIM);
    // 3. V transpose
    vt_kernel<<<dim3(SEQ / 32, HEADS, BATCH), tb>>>();
    // 4. flash attention (64-query blocks, 4/SM) -> fp16 [B, L, C]
    attn_h_kernel<<<dim3(SEQ / 64, HEADS, BATCH), 128>>>(attnout);
    // 5. xres = x + attnout @ proj_w + proj_b  (fp32)
    gemm_h<EPI_RES, 0><<<dim3(4, 64), 128>>>(attnout, w + W_PROJ, proj_b, x,
                                             xres, nullptr, MROWS, DIM, DIM);
    // 6. h = LN2(xres)
    ln_kernel<<<MROWS, 128>>>(xres, n2_g, n2_b, h);
    // 7. mlp1 = fp16(gelu(h @ fc1_w + fc1_b))
    gemm_h<EPI_GELU, 1><<<dim3(16, 64), 128>>>(h, w + W_FC1, fc1_b, nullptr,
                                               nullptr, mlp1, MROWS, MLPH, DIM);
    // 8. out = xres + mlp1 @ fc2_w + fc2_b  (fp32)
    gemm_h<EPI_RES, 0><<<dim3(4, 64), 128>>>(mlp1, w + W_FC2, fc2_b, xres,
                                             out, nullptr, MROWS, DIM, MLPH);
}

// round 14
// speedup vs baseline: 2.2495x; 1.1197x over previous
#include <cuda_runtime.h>
#include <cuda_fp16.h>
#include <math.h>
#include <stdint.h>

#define BATCH 8
#define SEQ 1024
#define DIM 512
#define HEADS 16
#define HD 32
#define MROWS (BATCH*SEQ)   /* 8192 */
#define MLPH 2048
#define TBLN 3969           /* (2*32-1)^2 */

// ---------------- scratch (device globals; no allocations allowed) ----------
__device__ __align__(256) __half g_h[MROWS * DIM];         // LN out (fp16)
__device__ __align__(256) __half g_qkv[MROWS * 3 * DIM];   // q|k|v (fp16)
__device__ __align__(256) __half g_vt[BATCH * HEADS * HD * SEQ]; // V^T per (b,h)
__device__ __align__(256) __half g_attnout[MROWS * DIM];   // attention out (fp16)
__device__ __align__(256) __half g_mlp1[MROWS * MLPH];     // gelu(fc1) (fp16)
__device__ __align__(256) __half g_w[3145728];             // [N][K] fp16 weights
__device__ float g_xres[MROWS * DIM];                      // x + proj(attn) fp32
__device__ float g_tblt[HEADS * TBLN];                     // transposed bias table

#define W_QKV  0
#define W_PROJ 786432
#define W_FC1  1048576
#define W_FC2  2097152

// ---------------- helpers ----------------------------------------------------
__device__ __forceinline__ void mma_f16(float* c, uint32_t a0, uint32_t a1,
                                        uint32_t a2, uint32_t a3,
                                        uint32_t b0, uint32_t b1) {
    asm volatile(
        "mma.sync.aligned.m16n8k16.row.col.f32.f16.f16.f32 "
        "{%0,%1,%2,%3}, {%4,%5,%6,%7}, {%8,%9}, {%0,%1,%2,%3};"
        : "+f"(c[0]), "+f"(c[1]), "+f"(c[2]), "+f"(c[3])
        : "r"(a0), "r"(a1), "r"(a2), "r"(a3), "r"(b0), "r"(b1));
}

__device__ __forceinline__ void ldsm4(uint32_t& r0, uint32_t& r1,
                                      uint32_t& r2, uint32_t& r3, uint32_t addr) {
    asm volatile("ldmatrix.sync.aligned.m8n8.x4.shared.b16 {%0,%1,%2,%3}, [%4];"
                 : "=r"(r0), "=r"(r1), "=r"(r2), "=r"(r3) : "r"(addr));
}

__device__ __forceinline__ void cp16(uint32_t s, const void* g) {
    asm volatile("cp.async.cg.shared.global [%0], [%1], 16;\n" :: "r"(s), "l"(g));
}
__device__ __forceinline__ void cp_commit() {
    asm volatile("cp.async.commit_group;\n");
}
template <int N> __device__ __forceinline__ void cp_wait() {
    asm volatile("cp.async.wait_group %0;\n" :: "n"(N));
}
__device__ __forceinline__ uint32_t smem_u32(const void* p) {
    uint32_t a;
    asm("{ .reg .u64 t; cvta.to.shared.u64 t, %1; cvt.u32.u64 %0, t; }"
        : "=r"(a) : "l"(p));
    return a;
}
__device__ __forceinline__ uint32_t pack_h2(float lo, float hi) {
    const __half2 h = __floats2half2_rn(lo, hi);
    return *(const uint32_t*)&h;
}

// ---------------- merged weight transpose + fp16 convert ---------------------
__global__ void __launch_bounds__(256) cvt_all_kernel(const float* __restrict__ qkv_w,
                                                      const float* __restrict__ proj_w,
                                                      const float* __restrict__ fc1_w,
                                                      const float* __restrict__ fc2_w,
                                                      __half* __restrict__ w)
{
    __shared__ float tile[32][33];
    const int bid = blockIdx.x;
    const float* in;
    __half* out;
    int K, N, tid2;
    if (bid < 768)       { in = qkv_w;  out = w + W_QKV;  K = DIM;  N = 3 * DIM; tid2 = bid; }
    else if (bid < 1024) { in = proj_w; out = w + W_PROJ; K = DIM;  N = DIM;     tid2 = bid - 768; }
    else if (bid < 2048) { in = fc1_w;  out = w + W_FC1;  K = DIM;  N = MLPH;    tid2 = bid - 1024; }
    else                 { in = fc2_w;  out = w + W_FC2;  K = MLPH; N = DIM;     tid2 = bid - 2048; }
    const int ntx = N >> 5;
    const int bn = (tid2 % ntx) * 32, bk = (tid2 / ntx) * 32;
    const int tx = threadIdx.x, ty = threadIdx.y;
    #pragma unroll
    for (int i = 0; i < 4; i++)
        tile[ty + 8 * i][tx] = in[(size_t)(bk + ty + 8 * i) * N + bn + tx];
    __syncthreads();
    #pragma unroll
    for (int i = 0; i < 4; i++) {
        const int n = ty + 8 * i;
        out[(size_t)(bn + n) * K + bk + tx] = __float2half_rn(tile[tx][n]);
    }
}

// ---------------- bias-table transpose ---------------------------------------
__global__ void __launch_bounds__(256) tblt_kernel(const float* __restrict__ table)
{
    const int i = blockIdx.x * 256 + threadIdx.x;
    if (i < TBLN) {
        #pragma unroll
        for (int h = 0; h < HEADS; h++)
            g_tblt[h * TBLN + i] = table[i * HEADS + h];
    }
}

// ---------------- V transpose ------------------------------------------------
__global__ void __launch_bounds__(256) vt_kernel()
{
    __shared__ __half tile[32][34];
    const int m0 = blockIdx.x * 32, h = blockIdx.y, b = blockIdx.z;
    const int tx = threadIdx.x, ty = threadIdx.y;
    const __half* in = g_qkv + (size_t)(b * SEQ) * (3 * DIM) + 2 * DIM + h * HD;
    #pragma unroll
    for (int i = 0; i < 4; i++)
        tile[ty + 8 * i][tx] = in[(size_t)(m0 + ty + 8 * i) * (3 * DIM) + tx];
    __syncthreads();
    __half* out = g_vt + ((size_t)(b * HEADS + h) * HD) * SEQ + m0;
    #pragma unroll
    for (int i = 0; i < 4; i++) {
        const int d = ty + 8 * i;
        out[(size_t)d * SEQ + tx] = tile[tx][d];
    }
}

// ---------------- LayerNorm (fp16 output) ------------------------------------
__global__ void __launch_bounds__(128) ln_kernel(const float* __restrict__ x,
                                                 const float* __restrict__ g,
                                                 const float* __restrict__ b,
                                                 __half* __restrict__ out)
{
    const int row = blockIdx.x;
    const int t = threadIdx.x;
    const float4 v = ((const float4*)(x + (size_t)row * DIM))[t];
    float s  = v.x + v.y + v.z + v.w;
    float s2 = v.x*v.x + v.y*v.y + v.z*v.z + v.w*v.w;
    #pragma unroll
    for (int o = 16; o > 0; o >>= 1) {
        s  += __shfl_xor_sync(0xffffffffu, s,  o);
        s2 += __shfl_xor_sync(0xffffffffu, s2, o);
    }
    __shared__ float rs[4], rs2[4];
    if ((t & 31) == 0) { rs[t >> 5] = s; rs2[t >> 5] = s2; }
    __syncthreads();
    s  = rs[0] + rs[1] + rs[2] + rs[3];
    s2 = rs2[0] + rs2[1] + rs2[2] + rs2[3];
    const float mean = s * (1.0f / DIM);
    const float var  = s2 * (1.0f / DIM) - mean * mean;
    const float inv  = rsqrtf(var + 1e-5f);
    const float4 gg = ((const float4*)g)[t];
    const float4 bb = ((const float4*)b)[t];
    __half2* op = (__half2*)(out + (size_t)row * DIM + 4 * t);
    op[0] = __floats2half2_rn((v.x - mean) * inv * gg.x + bb.x,
                              (v.y - mean) * inv * gg.y + bb.y);
    op[1] = __floats2half2_rn((v.z - mean) * inv * gg.z + bb.z,
                              (v.w - mean) * inv * gg.w + bb.w);
}

// ---------------- fp16 GEMM: ldmatrix frags, 3-stage cp.async ----------------
// C[M,N] = epilogue(A[M,K] @ Wt[N,K]^T + bias [, R])
// 128x128 block, BK=32, 128 thr = 4 warps (2x2), warp tile 64x64, m16n8k16.
enum { EPI_BIAS = 0, EPI_GELU = 1, EPI_RES = 2 };

template <int EPI, int OUTH>
__global__ void __launch_bounds__(128, 2) gemm_h(const __half* __restrict__ A,
                                                 const __half* __restrict__ Wt,
                                                 const float* __restrict__ bias,
                                                 const float* __restrict__ R,
                                                 float* __restrict__ Cf,
                                                 __half* __restrict__ Ch,
                                                 int M, int N, int K)
{
    __shared__ __align__(16) __half As[3][128][40];   // [m][k]
    __shared__ __align__(16) __half Bs[3][128][40];   // [n][k]

    const int bm = blockIdx.y * 128, bn = blockIdx.x * 128;
    const int tid = threadIdx.x;
    const int warp = tid >> 5, lane = tid & 31;
    const int wm = (warp & 1) * 64, wn = (warp >> 1) * 64;
    const int g = lane >> 2, t4 = lane & 3;

    const int srow = tid >> 2, sch = (tid & 3) * 8;

    // ldmatrix per-lane offsets (in halfs; row stride = 40 halfs)
    const int a_off = (wm + (lane & 15)) * 40 + (lane >> 4) * 8;              // + 16*ks + 16mi*40
    const int b_off = (wn + (lane & 7) + ((lane >> 4) & 1) * 8) * 40
                      + ((lane >> 3) & 1) * 8;                                 // + 16*ks + 16nj*40

    float acc[4][8][4];
    #pragma unroll
    for (int mi = 0; mi < 4; mi++)
        #pragma unroll
        for (int ni = 0; ni < 8; ni++)
            #pragma unroll
            for (int c = 0; c < 4; c++) acc[mi][ni][c] = 0.0f;

    const int nk = K >> 5;

    #pragma unroll
    for (int st = 0; st < 2; st++) {
        const int k0 = st * 32;
        #pragma unroll
        for (int i = 0; i < 4; i++) {
            const int r = srow + i * 32;
            cp16(smem_u32(&As[st][r][sch]), A + (size_t)(bm + r) * K + k0 + sch);
            cp16(smem_u32(&Bs[st][r][sch]), Wt + (size_t)(bn + r) * K + k0 + sch);
        }
        cp_commit();
    }

    int s = 0;
    for (int kt = 0; kt < nk; kt++) {
        if (kt + 2 < nk) {
            const int k0 = (kt + 2) * 32;
            const int sn = (s + 2) % 3;
            #pragma unroll
            for (int i = 0; i < 4; i++) {
                const int r = srow + i * 32;
                cp16(smem_u32(&As[sn][r][sch]), A + (size_t)(bm + r) * K + k0 + sch);
                cp16(smem_u32(&Bs[sn][r][sch]), Wt + (size_t)(bn + r) * K + k0 + sch);
            }
            cp_commit();
            cp_wait<2>();
        } else if (kt + 1 < nk) {
            cp_wait<1>();
        } else {
            cp_wait<0>();
        }
        __syncthreads();

        const uint32_t asb = smem_u32(&As[s][0][0]);
        const uint32_t bsb = smem_u32(&Bs[s][0][0]);

        #pragma unroll
        for (int ks = 0; ks < 2; ks++) {
            uint32_t a[4][4], bb[8][2];
            #pragma unroll
            for (int mi = 0; mi < 4; mi++)
                ldsm4(a[mi][0], a[mi][1], a[mi][2], a[mi][3],
                      asb + (uint32_t)(a_off + mi * 16 * 40 + ks * 16) * 2);
            #pragma unroll
            for (int nj = 0; nj < 4; nj++)
                ldsm4(bb[2 * nj][0], bb[2 * nj][1], bb[2 * nj + 1][0], bb[2 * nj + 1][1],
                      bsb + (uint32_t)(b_off + nj * 16 * 40 + ks * 16) * 2);
            #pragma unroll
            for (int ni = 0; ni < 8; ni++)
                #pragma unroll
                for (int mi = 0; mi < 4; mi++)
                    mma_f16(acc[mi][ni], a[mi][0], a[mi][1], a[mi][2], a[mi][3],
                            bb[ni][0], bb[ni][1]);
        }
        __syncthreads();
        s = (s + 1) % 3;
    }

    #pragma unroll
    for (int mi = 0; mi < 4; mi++) {
        const int r0 = bm + wm + mi * 16 + g;
        #pragma unroll
        for (int ni = 0; ni < 8; ni++) {
            const int col = bn + wn + ni * 8 + t4 * 2;
            const float b0 = bias[col], b1 = bias[col + 1];
            float v[4];
            v[0] = acc[mi][ni][0] + b0;
            v[1] = acc[mi][ni][1] + b1;
            v[2] = acc[mi][ni][2] + b0;
            v[3] = acc[mi][ni][3] + b1;
            if (EPI == EPI_GELU) {
                #pragma unroll
                for (int c = 0; c < 4; c++)
                    v[c] = 0.5f * v[c] * (1.0f + erff(v[c] * 0.70710678118654752f));
            }
            if (EPI == EPI_RES) {
                const float2 r4a = *(const float2*)(R + (size_t)r0 * N + col);
                const float2 r4b = *(const float2*)(R + (size_t)(r0 + 8) * N + col);
                v[0] += r4a.x; v[1] += r4a.y;
                v[2] += r4b.x; v[3] += r4b.y;
            }
            if (OUTH) {
                *(__half2*)(Ch + (size_t)r0 * N + col)       = __floats2half2_rn(v[0], v[1]);
                *(__half2*)(Ch + (size_t)(r0 + 8) * N + col) = __floats2half2_rn(v[2], v[3]);
            } else {
                *(float2*)(Cf + (size_t)r0 * N + col)       = make_float2(v[0], v[1]);
                *(float2*)(Cf + (size_t)(r0 + 8) * N + col) = make_float2(v[2], v[3]);
            }
        }
    }
}

// ---------------- Flash attention: ldmatrix frags, 64-q blocks, 4/SM ---------
#define NIT (SEQ / 64)

__global__ void __launch_bounds__(128, 4) attn_h_kernel(__half* __restrict__ out)
{
    __shared__ __align__(16) __half Ks[3][64][40];   // [key][d]
    __shared__ __align__(16) __half Vt[3][32][72];   // [d][key]
    __shared__ float tbl[TBLN];

    const int b = blockIdx.z, h = blockIdx.y, q0 = blockIdx.x * 64;
    const int tid = threadIdx.x;
    const int warp = tid >> 5, lane = tid & 31;
    const int g = lane >> 2, t4 = lane & 3;
    const int wq = warp * 16;

    const float scale = 0.17677669529663687f;  // 1/sqrt(32)

    // staging maps (128 threads)
    const int kkey = tid >> 2, kch = (tid & 3) * 8;
    const int vd = tid >> 3, vch = (tid & 7) * 8;

    const __half* kbase = g_qkv + (size_t)(b * SEQ + kkey) * (3 * DIM)
                          + DIM + h * HD + kch;
    const __half* vbase = g_vt + ((size_t)(b * HEADS + h) * HD + vd) * SEQ + vch;
    const size_t kstep = (size_t)32 * (3 * DIM);
    const size_t vstep = (size_t)16 * SEQ;

    // ldmatrix per-lane B offsets (halfs): rows (lane&7)+((lane>>4)&1)*8,
    // col ((lane>>3)&1)*8
    const int kb_off = ((lane & 7) + ((lane >> 4) & 1) * 8) * 40
                       + ((lane >> 3) & 1) * 8;                       // Ks stride 40
    const int vb_off = ((lane & 7) + ((lane >> 4) & 1) * 8) * 72
                       + ((lane >> 3) & 1) * 8;                       // Vt stride 72

    #pragma unroll
    for (int st = 0; st < 2; st++) {
        cp16(smem_u32(&Ks[st][kkey][kch]), kbase + (size_t)(st * 64) * (3 * DIM));
        cp16(smem_u32(&Ks[st][kkey + 32][kch]),
             kbase + (size_t)(st * 64) * (3 * DIM) + kstep);
        cp16(smem_u32(&Vt[st][vd][vch]), vbase + st * 64);
        cp16(smem_u32(&Vt[st][vd + 16][vch]), vbase + st * 64 + vstep);
        cp_commit();
    }

    {
        const float* tsrc = g_tblt + (size_t)h * TBLN;
        for (int i = tid; i < TBLN; i += 128) tbl[i] = tsrc[i];
    }

    // Q fragments (raw fp16; scale folded into post-mma FFMA)
    uint32_t qf[2][4];
    {
        const __half* q0p = g_qkv + (size_t)(b * SEQ + q0 + wq + g) * (3 * DIM) + h * HD;
        const __half* q1p = q0p + 8 * (3 * DIM);
        #pragma unroll
        for (int ks = 0; ks < 2; ks++) {
            const int kc = 16 * ks + 2 * t4;
            qf[ks][0] = *(const uint32_t*)(q0p + kc);
            qf[ks][1] = *(const uint32_t*)(q1p + kc);
            qf[ks][2] = *(const uint32_t*)(q0p + kc + 8);
            qf[ks][3] = *(const uint32_t*)(q1p + kc + 8);
        }
    }

    const int l0 = q0 + wq + g, l1 = l0 + 8;
    const int Cb0 = (l0 >> 5) * 63 + (l0 & 31) + 1984;
    const int Cb1 = (l1 >> 5) * 63 + (l1 & 31) + 1984;

    float m0 = -1e30f, m1 = -1e30f, li0 = 0.0f, li1 = 0.0f;
    float acc_o[4][4];
    #pragma unroll
    for (int ni = 0; ni < 4; ni++)
        #pragma unroll
        for (int c = 0; c < 4; c++) acc_o[ni][c] = 0.0f;

    for (int it = 0; it < NIT; it++) {
        const int s = it % 3;
        if (it + 1 < NIT) cp_wait<1>(); else cp_wait<0>();
        __syncthreads();
        if (it + 2 < NIT) {
            const int sn = (it + 2) % 3;
            const size_t ko = (size_t)((it + 2) * 64) * (3 * DIM);
            cp16(smem_u32(&Ks[sn][kkey][kch]), kbase + ko);
            cp16(smem_u32(&Ks[sn][kkey + 32][kch]), kbase + ko + kstep);
            cp16(smem_u32(&Vt[sn][vd][vch]), vbase + (it + 2) * 64);
            cp16(smem_u32(&Vt[sn][vd + 16][vch]), vbase + (it + 2) * 64 + vstep);
            cp_commit();
        }

        const uint32_t ksb = smem_u32(&Ks[s][0][0]);
        const uint32_t vsb = smem_u32(&Vt[s][0][0]);

        // ---- S = Q @ K^T ----
        float sacc[8][4];
        #pragma unroll
        for (int ni = 0; ni < 8; ni++)
            #pragma unroll
            for (int c = 0; c < 4; c++) sacc[ni][c] = 0.0f;
        #pragma unroll
        for (int ks = 0; ks < 2; ks++) {
            uint32_t kb[8][2];
            #pragma unroll
            for (int nj = 0; nj < 4; nj++)
                ldsm4(kb[2 * nj][0], kb[2 * nj][1], kb[2 * nj + 1][0], kb[2 * nj + 1][1],
                      ksb + (uint32_t)(kb_off + nj * 16 * 40 + ks * 16) * 2);
            #pragma unroll
            for (int ni = 0; ni < 8; ni++)
                mma_f16(sacc[ni], qf[ks][0], qf[ks][1], qf[ks][2], qf[ks][3],
                        kb[ni][0], kb[ni][1]);
        }
        // ---- scale + rel-pos bias ----
        const int k0 = it * 64;
        {
            const int base0 = Cb0 - (k0 >> 5) * 63;
            const int base1 = Cb1 - (k0 >> 5) * 63;
            #pragma unroll
            for (int ni = 0; ni < 8; ni++) {
                const int off = (ni >> 2) * 63 + 8 * (ni & 3) + 2 * t4;
                sacc[ni][0] = fmaf(sacc[ni][0], scale, tbl[base0 - off]);
                sacc[ni][1] = fmaf(sacc[ni][1], scale, tbl[base0 - off - 1]);
                sacc[ni][2] = fmaf(sacc[ni][2], scale, tbl[base1 - off]);
                sacc[ni][3] = fmaf(sacc[ni][3], scale, tbl[base1 - off - 1]);
            }
        }

        // ---- online softmax (registers only) ----
        float vmax0 = -1e30f, vmax1 = -1e30f;
        #pragma unroll
        for (int ni = 0; ni < 8; ni++) {
            vmax0 = fmaxf(vmax0, fmaxf(sacc[ni][0], sacc[ni][1]));
            vmax1 = fmaxf(vmax1, fmaxf(sacc[ni][2], sacc[ni][3]));
        }
        #pragma unroll
        for (int o = 1; o <= 2; o <<= 1) {
            vmax0 = fmaxf(vmax0, __shfl_xor_sync(0xffffffffu, vmax0, o));
            vmax1 = fmaxf(vmax1, __shfl_xor_sync(0xffffffffu, vmax1, o));
        }
        const float nm0 = fmaxf(m0, vmax0);
        const float nm1 = fmaxf(m1, vmax1);
        const float corr0 = __expf(m0 - nm0);
        const float corr1 = __expf(m1 - nm1);
        m0 = nm0; m1 = nm1;
        float rs0 = 0.0f, rs1 = 0.0f;

        uint32_t ph2[8][2];
        #pragma unroll
        for (int ni = 0; ni < 8; ni++) {
            const float p0 = __expf(sacc[ni][0] - m0);
            const float p1 = __expf(sacc[ni][1] - m0);
            const float p2 = __expf(sacc[ni][2] - m1);
            const float p3 = __expf(sacc[ni][3] - m1);
            rs0 += p0 + p1; rs1 += p2 + p3;
            ph2[ni][0] = pack_h2(p0, p1);
            ph2[ni][1] = pack_h2(p2, p3);
        }
        li0 = li0 * corr0 + rs0;
        li1 = li1 * corr1 + rs1;
        #pragma unroll
        for (int ni = 0; ni < 4; ni++) {
            acc_o[ni][0] *= corr0; acc_o[ni][1] *= corr0;
            acc_o[ni][2] *= corr1; acc_o[ni][3] *= corr1;
        }

        // ---- O += P @ V ----
        #pragma unroll
        for (int ks = 0; ks < 4; ks++) {
            uint32_t vb[4][2];
            #pragma unroll
            for (int nj = 0; nj < 2; nj++)
                ldsm4(vb[2 * nj][0], vb[2 * nj][1], vb[2 * nj + 1][0], vb[2 * nj + 1][1],
                      vsb + (uint32_t)(vb_off + nj * 16 * 72 + ks * 16) * 2);
            const uint32_t a0 = ph2[2 * ks][0];
            const uint32_t a1 = ph2[2 * ks][1];
            const uint32_t a2 = ph2[2 * ks + 1][0];
            const uint32_t a3 = ph2[2 * ks + 1][1];
            #pragma unroll
            for (int ni = 0; ni < 4; ni++)
                mma_f16(acc_o[ni], a0, a1, a2, a3, vb[ni][0], vb[ni][1]);
        }
    }

    // ---- finalize ----
    #pragma unroll
    for (int o = 1; o <= 2; o <<= 1) {
        li0 += __shfl_xor_sync(0xffffffffu, li0, o);
        li1 += __shfl_xor_sync(0xffffffffu, li1, o);
    }
    const float inv0 = 1.0f / li0;
    const float inv1 = 1.0f / li1;
    __half* o0p = out + (size_t)(b * SEQ + q0 + wq + g) * DIM + h * HD;
    __half* o1p = o0p + 8 * DIM;
    #pragma unroll
    for (int ni = 0; ni < 4; ni++) {
        const int col = ni * 8 + t4 * 2;
        *(__half2*)(o0p + col) = __floats2half2_rn(acc_o[ni][0] * inv0,
                                                   acc_o[ni][1] * inv0);
        *(__half2*)(o1p + col) = __floats2half2_rn(acc_o[ni][2] * inv1,
                                                   acc_o[ni][3] * inv1);
    }
}

// ---------------- launch -----------------------------------------------------
extern "C" void kernel_launch(void* const* d_in, const int* in_sizes, int n_in,
                              void* d_out, int out_size)
{
    const float* x      = (const float*)d_in[0];
    const float* table  = (const float*)d_in[2];
    const float* qkv_w  = (const float*)d_in[3];
    const float* qkv_b  = (const float*)d_in[4];
    const float* proj_w = (const float*)d_in[5];
    const float* proj_b = (const float*)d_in[6];
    const float* n1_g   = (const float*)d_in[7];
    const float* n1_b   = (const float*)d_in[8];
    const float* n2_g   = (const float*)d_in[9];
    const float* n2_b   = (const float*)d_in[10];
    const float* fc1_w  = (const float*)d_in[11];
    const float* fc1_b  = (const float*)d_in[12];
    const float* fc2_w  = (const float*)d_in[13];
    const float* fc2_b  = (const float*)d_in[14];
    float* out = (float*)d_out;

    __half *h, *qkv, *attnout, *mlp1, *w;
    float *xres;
    cudaGetSymbolAddress((void**)&h,       g_h);
    cudaGetSymbolAddress((void**)&qkv,     g_qkv);
    cudaGetSymbolAddress((void**)&attnout, g_attnout);
    cudaGetSymbolAddress((void**)&xres,    g_xres);
    cudaGetSymbolAddress((void**)&mlp1,    g_mlp1);
    cudaGetSymbolAddress((void**)&w,       g_w);

    dim3 tb(32, 8);
    cvt_all_kernel<<<3072, tb>>>(qkv_w, proj_w, fc1_w, fc2_w, w);
    tblt_kernel<<<(TBLN + 255) / 256, 256>>>(table);
    ln_kernel<<<MROWS, 128>>>(x, n1_g, n1_b, h);
    gemm_h<EPI_BIAS, 1><<<dim3(12, 64), 128>>>(h, w + W_QKV, qkv_b, nullptr,
                                               nullptr, qkv, MROWS, 3 * DIM, DIM);
    vt_kernel<<<dim3(SEQ / 32, HEADS, BATCH), tb>>>();
    attn_h_kernel<<<dim3(SEQ / 64, HEADS, BATCH), 128>>>(attnout);
    gemm_h<EPI_RES, 0><<<dim3(4, 64), 128>>>(attnout, w + W_PROJ, proj_b, x,
                                             xres, nullptr, MROWS, DIM, DIM);
    ln_kernel<<<MROWS, 128>>>(xres, n2_g, n2_b, h);
    gemm_h<EPI_GELU, 1><<<dim3(16, 64), 128>>>(h, w + W_FC1, fc1_b, nullptr,
                                               nullptr, mlp1, MROWS, MLPH, DIM);
    gemm_h<EPI_RES, 0><<<dim3(4, 64), 128>>>(mlp1, w + W_FC2, fc2_b, xres,
                                             out, nullptr, MROWS, DIM, MLPH);
}